// round 1
// baseline (speedup 1.0000x reference)
#include <cuda_runtime.h>
#include <math.h>

#define B   8
#define D   384
#define FD  256
#define NP  4096
#define NH  8
#define NC  4
#define HD  48
#define GS  1024
#define T   (B*NP)     /* 32768 tokens */
#define D4  1536
#define D2  768

// ---------------- scratch (device globals; no runtime allocation) ----------
static __device__ float g_gb1[B*D2];
static __device__ float g_gb2[B*D2];
static __device__ float g_gx[B*D];
static __device__ float g_gm[B];
static __device__ float g_A1[B*D];
static __device__ float g_C1[B*D];
static __device__ float g_A2[B*D];
static __device__ float g_C2[B*D];
static __device__ float g_gx2[B*D];
static __device__ float g_part[B*16*D];
static __device__ int   g_invp[NP];
static __device__ float g_imtok[(size_t)T*D];
static __device__ float g_xg[(size_t)T*D];     // also reused as attention output
static __device__ float g_q[(size_t)T*D];
static __device__ float g_k[(size_t)T*D];
static __device__ float g_v[(size_t)T*D];
static __device__ float g_ao[(size_t)T*D];
static __device__ float g_wi[(size_t)T*D];
static __device__ float g_x2[(size_t)T*D];
static __device__ float g_fo[(size_t)T*D];
static __device__ float g_h1[(size_t)T*D4];
static __device__ float g_kv[B*NC*NH*HD*HD];
static __device__ float g_ks[B*NC*NH*HD];

// ---------------- small helpers --------------------------------------------
__device__ __forceinline__ float blockReduce384(float v, float* sdata) {
    // blockDim.x == 384, sdata has 512 floats
    int tid = threadIdx.x;
    sdata[tid] = v;
    if (tid < 128) sdata[384 + tid] = 0.f;
    __syncthreads();
    #pragma unroll
    for (int s = 256; s >= 1; s >>= 1) {
        if (tid < s) sdata[tid] += sdata[tid + s];
        __syncthreads();
    }
    float r = sdata[0];
    __syncthreads();
    return r;
}

// ---------------- kernels ---------------------------------------------------
__global__ void k_invperm(const int* __restrict__ perm, int* __restrict__ invp) {
    int i = blockIdx.x * blockDim.x + threadIdx.x;
    if (i < NP) invp[perm[i]] = i;
}

// gb = film @ W^T + b  (for both adaln heads). 2 * B * 768 outputs.
__global__ void k_film(const float* __restrict__ film,
                       const float* __restrict__ W1, const float* __restrict__ b1,
                       const float* __restrict__ W2, const float* __restrict__ b2,
                       float* __restrict__ gb1, float* __restrict__ gb2) {
    int o = blockIdx.x * blockDim.x + threadIdx.x;
    if (o >= 2 * B * D2) return;
    int which = o / (B * D2);
    int r = o % (B * D2);
    int b = r / D2, j = r % D2;
    const float* W = which ? W2 : W1;
    const float* bb = which ? b2 : b1;
    const float* f = film + b * FD;
    const float* w = W + (size_t)j * FD;
    float s = 0.f;
    #pragma unroll 8
    for (int i = 0; i < FD; i++) s += f[i] * w[i];
    s += bb[j];
    if (which) gb2[r] = s; else gb1[r] = s;
}

// per-(b,d) L2 norm over contiguous NP pixels (image layout)
__global__ void k_gx_img(const float* __restrict__ img, float* __restrict__ gx) {
    __shared__ float sdata[256];
    int bd = blockIdx.x;
    const float* p = img + (size_t)bd * NP;
    float s = 0.f;
    for (int i = threadIdx.x; i < NP; i += 256) { float v = p[i]; s += v * v; }
    sdata[threadIdx.x] = s; __syncthreads();
    for (int st = 128; st >= 1; st >>= 1) {
        if (threadIdx.x < st) sdata[threadIdx.x] += sdata[threadIdx.x + st];
        __syncthreads();
    }
    if (threadIdx.x == 0) gx[bd] = sqrtf(sdata[0]);
}

__global__ void k_gmean(const float* __restrict__ gx, float* __restrict__ gm) {
    __shared__ float sdata[512];
    int b = blockIdx.x;
    float v = gx[b * D + threadIdx.x];
    float s = blockReduce384(v, sdata);
    if (threadIdx.x == 0) gm[b] = s / (float)D;
}

// A[b,d] = ((1+g_d)*nx + 1)*(1+gamma);  C[b,d] = b_d*(1+gamma) + beta
__global__ void k_coef(const float* __restrict__ gx, const float* __restrict__ gm,
                       const float* __restrict__ gg, const float* __restrict__ gb_,
                       const float* __restrict__ gbmat,
                       float* __restrict__ A, float* __restrict__ C) {
    int idx = blockIdx.x * blockDim.x + threadIdx.x;
    if (idx >= B * D) return;
    int b = idx / D, d = idx % D;
    float nx = gx[idx] / (gm[b] + 1e-6f);
    float gamma = gbmat[b * D2 + d];
    float beta  = gbmat[b * D2 + D + d];
    A[idx] = ((1.f + gg[d]) * nx + 1.f) * (1.f + gamma);
    C[idx] = gb_[d] * (1.f + gamma) + beta;
}

// gather pixels -> token-major; also store raw gathered image
__global__ void k_gather(const float* __restrict__ img, const int* __restrict__ perm,
                         const float* __restrict__ A, const float* __restrict__ C,
                         float* __restrict__ imtok, float* __restrict__ xg) {
    int t = blockIdx.x;          // 0..T-1
    int d = threadIdx.x;         // 0..383
    int b = t >> 12;
    int tt = t & (NP - 1);
    int pix = perm[tt];
    float v = img[((size_t)b * D + d) * NP + pix];
    size_t o = (size_t)t * D + d;
    imtok[o] = v;
    xg[o] = A[b * D + d] * v + C[b * D + d];
}

// ---- fp32 tiled GEMM: C[M,N] = A[M,K] @ W[N,K]^T + bias ; act: 0=none 1=silu
#define BM 128
#define BN 128
#define BK 16
__global__ void __launch_bounds__(256) gemm_nt(const float* __restrict__ A,
                                               const float* __restrict__ W,
                                               const float* __restrict__ bias,
                                               float* __restrict__ C,
                                               int M, int N, int K, int act) {
    __shared__ float As[BK][BM];
    __shared__ float Ws[BK][BN];
    int tid = threadIdx.x;
    int m0 = blockIdx.y * BM, n0 = blockIdx.x * BN;
    int tm = tid >> 4, tn = tid & 15;
    float acc[8][8];
    #pragma unroll
    for (int i = 0; i < 8; i++)
        #pragma unroll
        for (int j = 0; j < 8; j++) acc[i][j] = 0.f;

    for (int k0 = 0; k0 < K; k0 += BK) {
        #pragma unroll
        for (int l = 0; l < 2; l++) {
            int idx = tid + l * 256;        // 0..511
            int row = idx >> 2;             // 0..127
            int kq = (idx & 3) * 4;
            float4 av = *(const float4*)(A + (size_t)(m0 + row) * K + k0 + kq);
            As[kq + 0][row] = av.x; As[kq + 1][row] = av.y;
            As[kq + 2][row] = av.z; As[kq + 3][row] = av.w;
            float4 wv = *(const float4*)(W + (size_t)(n0 + row) * K + k0 + kq);
            Ws[kq + 0][row] = wv.x; Ws[kq + 1][row] = wv.y;
            Ws[kq + 2][row] = wv.z; Ws[kq + 3][row] = wv.w;
        }
        __syncthreads();
        #pragma unroll
        for (int kk = 0; kk < BK; kk++) {
            float a[8], bb[8];
            #pragma unroll
            for (int i = 0; i < 8; i++) a[i] = As[kk][tm * 8 + i];
            #pragma unroll
            for (int j = 0; j < 8; j++) bb[j] = Ws[kk][tn * 8 + j];
            #pragma unroll
            for (int i = 0; i < 8; i++)
                #pragma unroll
                for (int j = 0; j < 8; j++) acc[i][j] += a[i] * bb[j];
        }
        __syncthreads();
    }
    #pragma unroll
    for (int i = 0; i < 8; i++) {
        int m = m0 + tm * 8 + i;
        #pragma unroll
        for (int j = 0; j < 8; j++) {
            int n = n0 + tn * 8 + j;
            float c = acc[i][j] + bias[n];
            if (act == 1) c = c / (1.f + expf(-c));
            C[(size_t)m * N + n] = c;
        }
    }
}

// per-token LayerNorm over D then elu+1 (in place)
__global__ void k_lnelu(float* __restrict__ X, const float* __restrict__ g,
                        const float* __restrict__ bb) {
    __shared__ float sdata[512];
    int t = blockIdx.x, d = threadIdx.x;
    size_t o = (size_t)t * D + d;
    float v = X[o];
    float mean = blockReduce384(v, sdata) / (float)D;
    float sq = blockReduce384(v * v, sdata) / (float)D;
    float var = sq - mean * mean;
    float y = (v - mean) * rsqrtf(var + 1e-5f) * g[d] + bb[d];
    X[o] = (y > 0.f) ? (y + 1.f) : expf(y);
}

// kv[bh] = sum_i k_i outer v_i ; ksum[bh] = sum_i k_i
__global__ void __launch_bounds__(256) k_attn_kv(const float* __restrict__ k,
                                                 const float* __restrict__ v,
                                                 float* __restrict__ kv,
                                                 float* __restrict__ ksum) {
    int bh = blockIdx.x;          // bc*NH + h
    int h = bh & (NH - 1), bc = bh >> 3;
    __shared__ float sk[16][HD];
    __shared__ float sv[16][HD];
    int tid = threadIdx.x;
    float acc[9];
    #pragma unroll
    for (int p = 0; p < 9; p++) acc[p] = 0.f;
    float ks = 0.f;
    int base = tid * 9;
    int dp[9], ep[9];
    #pragma unroll
    for (int p = 0; p < 9; p++) { dp[p] = (base + p) / HD; ep[p] = (base + p) % HD; }

    for (int c = 0; c < GS / 16; c++) {
        int tt0 = bc * GS + c * 16;
        #pragma unroll
        for (int r = 0; r < 3; r++) {
            int j = r * 256 + tid;
            int ti = j / HD, d = j % HD;
            size_t src = (size_t)(tt0 + ti) * D + h * HD + d;
            sk[ti][d] = k[src];
            sv[ti][d] = v[src];
        }
        __syncthreads();
        #pragma unroll 4
        for (int ti = 0; ti < 16; ti++) {
            #pragma unroll
            for (int p = 0; p < 9; p++) acc[p] += sk[ti][dp[p]] * sv[ti][ep[p]];
        }
        if (tid < HD) {
            #pragma unroll 4
            for (int ti = 0; ti < 16; ti++) ks += sk[ti][tid];
        }
        __syncthreads();
    }
    #pragma unroll
    for (int p = 0; p < 9; p++) kv[(size_t)bh * HD * HD + base + p] = acc[p];
    if (tid < HD) ksum[bh * HD + tid] = ks;
}

// out[t,h,e] = (q . kv[:,e]) / (q . ksum + 1e-8)
__global__ void __launch_bounds__(256) k_attn_apply(const float* __restrict__ q,
                                                    const float* __restrict__ kv,
                                                    const float* __restrict__ ksum,
                                                    float* __restrict__ out) {
    int bh = blockIdx.x;               // bc*NH + h
    int tile = blockIdx.y;             // 0..15  (64 tokens each)
    int h = bh & (NH - 1), bc = bh >> 3;
    __shared__ float skv[HD * HD];
    __shared__ float sks[HD];
    __shared__ float sq[16][HD];
    int tid = threadIdx.x;
    for (int i = tid; i < HD * HD; i += 256) skv[i] = kv[(size_t)bh * HD * HD + i];
    if (tid < HD) sks[tid] = ksum[bh * HD + tid];
    __syncthreads();
    int t0 = bc * GS + tile * 64;
    for (int sub = 0; sub < 4; sub++) {
        int tt0 = t0 + sub * 16;
        #pragma unroll
        for (int r = 0; r < 3; r++) {
            int j = r * 256 + tid;
            int ti = j / HD, d = j % HD;
            sq[ti][d] = q[(size_t)(tt0 + ti) * D + h * HD + d];
        }
        __syncthreads();
        #pragma unroll
        for (int r = 0; r < 3; r++) {
            int j = r * 256 + tid;
            int ti = j / HD, e = j % HD;
            float num = 0.f, den = 0.f;
            #pragma unroll
            for (int d = 0; d < HD; d++) {
                float qq = sq[ti][d];
                num += qq * skv[d * HD + e];
                den += qq * sks[d];
            }
            out[(size_t)(tt0 + ti) * D + h * HD + e] = num / (den + 1e-8f);
        }
        __syncthreads();
    }
}

// wi = imtok + ao * cloud_scalar[d]
__global__ void k_wi(const float* __restrict__ imtok, const float* __restrict__ ao,
                     const float* __restrict__ cs, float* __restrict__ wi) {
    size_t idx = (size_t)blockIdx.x * 256 + threadIdx.x;
    int d = (int)(idx % D);
    wi[idx] = imtok[idx] + ao[idx] * cs[d];
}

// partial sums of wi^2 over token slices (token-major, coalesced over d)
__global__ void k_gx2part(const float* __restrict__ wi, float* __restrict__ part) {
    int b = blockIdx.x, dbase = blockIdx.y * 128, slice = blockIdx.z;
    int d = dbase + threadIdx.x;
    float s = 0.f;
    int t0 = slice * 256;
    for (int t = 0; t < 256; t++) {
        float v = wi[(size_t)(b * NP + t0 + t) * D + d];
        s += v * v;
    }
    part[(size_t)(b * 16 + slice) * D + d] = s;
}

__global__ void k_gx2red(const float* __restrict__ part, float* __restrict__ gx2) {
    int b = blockIdx.x, d = blockIdx.y * 128 + threadIdx.x;
    float s = 0.f;
    #pragma unroll
    for (int sl = 0; sl < 16; sl++) s += part[(size_t)(b * 16 + sl) * D + d];
    gx2[b * D + d] = sqrtf(s);
}

// x2 = A2[b,d]*wi + C2[b,d]
__global__ void k_x2(const float* __restrict__ wi, const float* __restrict__ A,
                     const float* __restrict__ C, float* __restrict__ x2) {
    size_t idx = (size_t)blockIdx.x * 256 + threadIdx.x;
    int t = (int)(idx / D), d = (int)(idx % D);
    int b = t >> 12;
    x2[idx] = A[b * D + d] * wi[idx] + C[b * D + d];
}

// wi += fo * ffn_scalar[d]
__global__ void k_wfo(float* __restrict__ wi, const float* __restrict__ fo,
                      const float* __restrict__ ffs) {
    size_t idx = (size_t)blockIdx.x * 256 + threadIdx.x;
    int d = (int)(idx % D);
    wi[idx] += fo[idx] * ffs[d];
}

// out[b,d,pix] = image[b,d,pix] + wi_tok[invp[pix] token, d] * final_scalar[d]
__global__ void k_final(const float* __restrict__ img, const float* __restrict__ wi,
                        const int* __restrict__ invp, const float* __restrict__ fs,
                        float* __restrict__ out) {
    size_t idx = (size_t)blockIdx.x * 256 + threadIdx.x;
    int pix = (int)(idx & (NP - 1));
    int bd = (int)(idx >> 12);
    int d = bd % D, b = bd / D;
    int t = b * NP + invp[pix];
    out[idx] = img[idx] + wi[(size_t)t * D + d] * fs[d];
}

// ---------------- driver ----------------------------------------------------
extern "C" void kernel_launch(void* const* d_in, const int* in_sizes, int n_in,
                              void* d_out, int out_size) {
    const float* image  = (const float*)d_in[0];
    const float* film   = (const float*)d_in[1];
    const int*   perm   = (const int*)d_in[2];
    const float* Wq = (const float*)d_in[3];  const float* bq = (const float*)d_in[4];
    const float* Wk = (const float*)d_in[5];  const float* bk = (const float*)d_in[6];
    const float* Wv = (const float*)d_in[7];  const float* bv = (const float*)d_in[8];
    const float* Wo = (const float*)d_in[9];  const float* bo = (const float*)d_in[10];
    const float* lnq_g = (const float*)d_in[11]; const float* lnq_b = (const float*)d_in[12];
    const float* lnk_g = (const float*)d_in[13]; const float* lnk_b = (const float*)d_in[14];
    const float* ada1_W = (const float*)d_in[15]; const float* ada1_b = (const float*)d_in[16];
    const float* grn1_g = (const float*)d_in[17]; const float* grn1_b = (const float*)d_in[18];
    const float* ada2_W = (const float*)d_in[19]; const float* ada2_b = (const float*)d_in[20];
    const float* grn2_g = (const float*)d_in[21]; const float* grn2_b = (const float*)d_in[22];
    const float* conv1_W = (const float*)d_in[23]; const float* conv1_b = (const float*)d_in[24];
    const float* conv2_W = (const float*)d_in[25]; const float* conv2_b = (const float*)d_in[26];
    const float* cs  = (const float*)d_in[27];
    const float* ffs = (const float*)d_in[28];
    const float* fs  = (const float*)d_in[29];
    float* out = (float*)d_out;

    float *p_gb1, *p_gb2, *p_gx, *p_gm, *p_A1, *p_C1, *p_A2, *p_C2, *p_gx2, *p_part;
    int* p_invp;
    float *p_imtok, *p_xg, *p_q, *p_k, *p_v, *p_ao, *p_wi, *p_x2, *p_fo, *p_h1, *p_kv, *p_ks;
    cudaGetSymbolAddress((void**)&p_gb1, g_gb1);
    cudaGetSymbolAddress((void**)&p_gb2, g_gb2);
    cudaGetSymbolAddress((void**)&p_gx, g_gx);
    cudaGetSymbolAddress((void**)&p_gm, g_gm);
    cudaGetSymbolAddress((void**)&p_A1, g_A1);
    cudaGetSymbolAddress((void**)&p_C1, g_C1);
    cudaGetSymbolAddress((void**)&p_A2, g_A2);
    cudaGetSymbolAddress((void**)&p_C2, g_C2);
    cudaGetSymbolAddress((void**)&p_gx2, g_gx2);
    cudaGetSymbolAddress((void**)&p_part, g_part);
    cudaGetSymbolAddress((void**)&p_invp, g_invp);
    cudaGetSymbolAddress((void**)&p_imtok, g_imtok);
    cudaGetSymbolAddress((void**)&p_xg, g_xg);
    cudaGetSymbolAddress((void**)&p_q, g_q);
    cudaGetSymbolAddress((void**)&p_k, g_k);
    cudaGetSymbolAddress((void**)&p_v, g_v);
    cudaGetSymbolAddress((void**)&p_ao, g_ao);
    cudaGetSymbolAddress((void**)&p_wi, g_wi);
    cudaGetSymbolAddress((void**)&p_x2, g_x2);
    cudaGetSymbolAddress((void**)&p_fo, g_fo);
    cudaGetSymbolAddress((void**)&p_h1, g_h1);
    cudaGetSymbolAddress((void**)&p_kv, g_kv);
    cudaGetSymbolAddress((void**)&p_ks, g_ks);

    const size_t ED = (size_t)T * D;           // 12.58M elements
    const int EW = (int)(ED / 256);            // 49152 blocks for elementwise

    k_invperm<<<16, 256>>>(perm, p_invp);
    k_film<<<48, 256>>>(film, ada1_W, ada1_b, ada2_W, ada2_b, p_gb1, p_gb2);
    k_gx_img<<<B * D, 256>>>(image, p_gx);
    k_gmean<<<B, 384>>>(p_gx, p_gm);
    k_coef<<<(B * D + 255) / 256, 256>>>(p_gx, p_gm, grn1_g, grn1_b, p_gb1, p_A1, p_C1);
    k_gather<<<T, 384>>>(image, perm, p_A1, p_C1, p_imtok, p_xg);

    gemm_nt<<<dim3(D / BN, T / BM), 256>>>(p_xg, Wq, bq, p_q, T, D, D, 0);
    gemm_nt<<<dim3(D / BN, T / BM), 256>>>(p_xg, Wk, bk, p_k, T, D, D, 0);
    gemm_nt<<<dim3(D / BN, T / BM), 256>>>(p_xg, Wv, bv, p_v, T, D, D, 0);

    k_lnelu<<<T, 384>>>(p_q, lnq_g, lnq_b);
    k_lnelu<<<T, 384>>>(p_k, lnk_g, lnk_b);

    k_attn_kv<<<B * NC * NH, 256>>>(p_k, p_v, p_kv, p_ks);
    k_attn_apply<<<dim3(B * NC * NH, 16), 256>>>(p_q, p_kv, p_ks, p_xg);

    gemm_nt<<<dim3(D / BN, T / BM), 256>>>(p_xg, Wo, bo, p_ao, T, D, D, 0);

    k_wi<<<EW, 256>>>(p_imtok, p_ao, cs, p_wi);

    k_gx2part<<<dim3(B, 3, 16), 128>>>(p_wi, p_part);
    k_gx2red<<<dim3(B, 3), 128>>>(p_part, p_gx2);
    k_gmean<<<B, 384>>>(p_gx2, p_gm);
    k_coef<<<(B * D + 255) / 256, 256>>>(p_gx2, p_gm, grn2_g, grn2_b, p_gb2, p_A2, p_C2);
    k_x2<<<EW, 256>>>(p_wi, p_A2, p_C2, p_x2);

    gemm_nt<<<dim3(D4 / BN, T / BM), 256>>>(p_x2, conv1_W, conv1_b, p_h1, T, D4, D, 1);
    gemm_nt<<<dim3(D / BN, T / BM), 256>>>(p_h1, conv2_W, conv2_b, p_fo, T, D, D4, 0);

    k_wfo<<<EW, 256>>>(p_wi, p_fo, ffs);
    k_final<<<EW, 256>>>(image, p_wi, p_invp, fs, out);
}

// round 2
// speedup vs baseline: 3.4750x; 3.4750x over previous
#include <cuda_runtime.h>
#include <cuda_bf16.h>
#include <math.h>
#include <stdint.h>

#define B   8
#define D   384
#define FD  256
#define NP  4096
#define NH  8
#define NC  4
#define HD  48
#define GS  1024
#define T   (B*NP)     /* 32768 tokens */
#define D4  1536
#define D2  768

typedef __nv_bfloat16 bf16;
typedef __nv_bfloat162 bf162;

// ---------------- scratch (device globals) ----------------------------------
static __device__ float g_gb1[B*D2];
static __device__ float g_gb2[B*D2];
static __device__ float g_gx[B*D];
static __device__ float g_gm[B];
static __device__ float g_A1[B*D];
static __device__ float g_C1[B*D];
static __device__ float g_A2[B*D];
static __device__ float g_C2[B*D];
static __device__ float g_gx2[B*D];
static __device__ float g_part[B*16*D];
static __device__ int   g_invp[NP];
static __device__ float g_imtok[(size_t)T*D];
static __device__ float g_q[(size_t)T*D];
static __device__ float g_k[(size_t)T*D];
static __device__ float g_v[(size_t)T*D];
static __device__ float g_wi[(size_t)T*D];
static __device__ float g_wif[(size_t)T*D];
static __device__ float g_kv[B*NC*NH*HD*HD];
static __device__ float g_ks[B*NC*NH*HD];
// bf16 activations
static __device__ bf16  g_xg16[(size_t)T*D];
static __device__ bf16  g_att16[(size_t)T*D];
static __device__ bf16  g_x216[(size_t)T*D];
static __device__ bf16  g_h116[(size_t)T*D4];
// bf16 weights
static __device__ bf16  g_wq16[D*D];
static __device__ bf16  g_wk16[D*D];
static __device__ bf16  g_wv16[D*D];
static __device__ bf16  g_wo16[D*D];
static __device__ bf16  g_c1w16[D4*D];
static __device__ bf16  g_c2w16[D*D4];

// ---------------- helpers ----------------------------------------------------
__device__ __forceinline__ uint32_t sptr(const void* p) {
    return (uint32_t)__cvta_generic_to_shared(p);
}
__device__ __forceinline__ void cp16(void* s, const void* g) {
    asm volatile("cp.async.cg.shared.global [%0], [%1], 16;\n"
                 :: "r"(sptr(s)), "l"(g));
}
__device__ __forceinline__ void cp_commit() {
    asm volatile("cp.async.commit_group;\n");
}
template<int N>
__device__ __forceinline__ void cp_wait() {
    asm volatile("cp.async.wait_group %0;\n" :: "n"(N));
}
__device__ __forceinline__ void mma16816(float* c, const uint32_t* a, const uint32_t* b) {
    asm volatile(
        "mma.sync.aligned.m16n8k16.row.col.f32.bf16.bf16.f32 "
        "{%0,%1,%2,%3}, {%4,%5,%6,%7}, {%8,%9}, {%0,%1,%2,%3};\n"
        : "+f"(c[0]), "+f"(c[1]), "+f"(c[2]), "+f"(c[3])
        : "r"(a[0]), "r"(a[1]), "r"(a[2]), "r"(a[3]), "r"(b[0]), "r"(b[1]));
}

__device__ __forceinline__ float blockReduce384(float v, float* sdata) {
    int tid = threadIdx.x;
    sdata[tid] = v;
    if (tid < 128) sdata[384 + tid] = 0.f;
    __syncthreads();
    #pragma unroll
    for (int s = 256; s >= 1; s >>= 1) {
        if (tid < s) sdata[tid] += sdata[tid + s];
        __syncthreads();
    }
    float r = sdata[0];
    __syncthreads();
    return r;
}

// ---------------- small kernels ----------------------------------------------
__global__ void k_invperm(const int* __restrict__ perm, int* __restrict__ invp) {
    int i = blockIdx.x * blockDim.x + threadIdx.x;
    if (i < NP) invp[perm[i]] = i;
}

__global__ void k_cvt(const float* __restrict__ src, bf16* __restrict__ dst, int n) {
    int i = blockIdx.x * blockDim.x + threadIdx.x;
    if (i < n) dst[i] = __float2bfloat16(src[i]);
}

__global__ void k_film(const float* __restrict__ film,
                       const float* __restrict__ W1, const float* __restrict__ b1,
                       const float* __restrict__ W2, const float* __restrict__ b2,
                       float* __restrict__ gb1, float* __restrict__ gb2) {
    int o = blockIdx.x * blockDim.x + threadIdx.x;
    if (o >= 2 * B * D2) return;
    int which = o / (B * D2);
    int r = o % (B * D2);
    int b = r / D2, j = r % D2;
    const float* W = which ? W2 : W1;
    const float* bb = which ? b2 : b1;
    const float* f = film + b * FD;
    const float* w = W + (size_t)j * FD;
    float s = 0.f;
    #pragma unroll 8
    for (int i = 0; i < FD; i++) s += f[i] * w[i];
    s += bb[j];
    if (which) gb2[r] = s; else gb1[r] = s;
}

__global__ void k_gx_img(const float* __restrict__ img, float* __restrict__ gx) {
    __shared__ float sdata[256];
    int bd = blockIdx.x;
    const float* p = img + (size_t)bd * NP;
    float s = 0.f;
    for (int i = threadIdx.x; i < NP; i += 256) { float v = p[i]; s += v * v; }
    sdata[threadIdx.x] = s; __syncthreads();
    for (int st = 128; st >= 1; st >>= 1) {
        if (threadIdx.x < st) sdata[threadIdx.x] += sdata[threadIdx.x + st];
        __syncthreads();
    }
    if (threadIdx.x == 0) gx[bd] = sqrtf(sdata[0]);
}

__global__ void k_gmean(const float* __restrict__ gx, float* __restrict__ gm) {
    __shared__ float sdata[512];
    int b = blockIdx.x;
    float v = gx[b * D + threadIdx.x];
    float s = blockReduce384(v, sdata);
    if (threadIdx.x == 0) gm[b] = s / (float)D;
}

__global__ void k_coef(const float* __restrict__ gx, const float* __restrict__ gm,
                       const float* __restrict__ gg, const float* __restrict__ gb_,
                       const float* __restrict__ gbmat,
                       float* __restrict__ A, float* __restrict__ C) {
    int idx = blockIdx.x * blockDim.x + threadIdx.x;
    if (idx >= B * D) return;
    int b = idx / D, d = idx % D;
    float nx = gx[idx] / (gm[b] + 1e-6f);
    float gamma = gbmat[b * D2 + d];
    float beta  = gbmat[b * D2 + D + d];
    A[idx] = ((1.f + gg[d]) * nx + 1.f) * (1.f + gamma);
    C[idx] = gb_[d] * (1.f + gamma) + beta;
}

// transpose-gather: image [b,d,pix] -> token-major imtok fp32 + xg bf16 (adaln applied)
__global__ void __launch_bounds__(256) k_gather_t(
        const float* __restrict__ img, const int* __restrict__ invp,
        const float* __restrict__ A, const float* __restrict__ C,
        float* __restrict__ imtok, bf16* __restrict__ xg) {
    __shared__ float tile[64][65];
    __shared__ int sinv[64];
    int p0 = blockIdx.x * 64, d0 = blockIdx.y * 64, b = blockIdx.z;
    int tid = threadIdx.x;
    if (tid < 64) sinv[tid] = invp[p0 + tid];
    #pragma unroll
    for (int l = 0; l < 4; l++) {
        int j = tid + l * 256;
        int i = j >> 4, q = (j & 15) * 4;
        float4 v = *(const float4*)(img + ((size_t)(b * D + d0 + i)) * NP + p0 + q);
        tile[i][q + 0] = v.x; tile[i][q + 1] = v.y;
        tile[i][q + 2] = v.z; tile[i][q + 3] = v.w;
    }
    __syncthreads();
    #pragma unroll
    for (int l = 0; l < 4; l++) {
        int j = tid + l * 256;
        int jp = j >> 4, i4 = (j & 15) * 4;
        int t = sinv[jp];
        size_t o = ((size_t)(b * NP + t)) * D + d0 + i4;
        float vv[4], xv[4];
        #pragma unroll
        for (int r = 0; r < 4; r++) {
            vv[r] = tile[i4 + r][jp];
            int cidx = b * D + d0 + i4 + r;
            xv[r] = A[cidx] * vv[r] + C[cidx];
        }
        *(float4*)&imtok[o] = make_float4(vv[0], vv[1], vv[2], vv[3]);
        bf162 h0 = __floats2bfloat162_rn(xv[0], xv[1]);
        bf162 h1 = __floats2bfloat162_rn(xv[2], xv[3]);
        *(bf162*)&xg[o] = h0;
        *(bf162*)&xg[o + 2] = h1;
    }
}

// ---------------- bf16 tensor-core GEMM: C = act(A @ W^T + bias) [+res*scale] -
// A: [M,K] bf16 row-major, W: [N,K] bf16 row-major. BM=BN=128, BK=32, 256 thr.
#define LDT 40
template<typename OutT, bool SILU, bool RES>
__global__ void __launch_bounds__(256) gemm_mma(
        const bf16* __restrict__ A, const bf16* __restrict__ W,
        const float* __restrict__ bias, const float* __restrict__ res,
        const float* __restrict__ scale, OutT* __restrict__ C,
        int M, int N, int K) {
    __shared__ bf16 sA[2][128 * LDT];
    __shared__ bf16 sW[2][128 * LDT];
    int tid = threadIdx.x;
    int m0 = blockIdx.y * 128, n0 = blockIdx.x * 128;
    int lane = tid & 31, warp = tid >> 5;
    int g = lane >> 2, tg = lane & 3;
    int wm = warp >> 2, wn = warp & 3;

    float acc[4][4][4];
    #pragma unroll
    for (int i = 0; i < 4; i++)
        #pragma unroll
        for (int j = 0; j < 4; j++)
            #pragma unroll
            for (int p = 0; p < 4; p++) acc[i][j][p] = 0.f;

    int nt = K / 32;
    auto issue = [&](int t, int s) {
        int k0 = t * 32;
        #pragma unroll
        for (int l = 0; l < 2; l++) {
            int j = tid + l * 256;
            int row = j >> 2, q = (j & 3) * 8;
            cp16(&sA[s][row * LDT + q], A + (size_t)(m0 + row) * K + k0 + q);
            cp16(&sW[s][row * LDT + q], W + (size_t)(n0 + row) * K + k0 + q);
        }
        cp_commit();
    };

    issue(0, 0);
    for (int t = 0; t < nt; t++) {
        int s = t & 1;
        if (t + 1 < nt) { issue(t + 1, (t + 1) & 1); cp_wait<1>(); }
        else            { cp_wait<0>(); }
        __syncthreads();
        const bf16* As = sA[s];
        const bf16* Ws = sW[s];
        #pragma unroll
        for (int kk = 0; kk < 32; kk += 16) {
            uint32_t af[4][4], bf[4][2];
            #pragma unroll
            for (int im = 0; im < 4; im++) {
                int r = wm * 64 + im * 16 + g;
                const bf16* p = As + r * LDT + kk + tg * 2;
                af[im][0] = *(const uint32_t*)p;
                af[im][1] = *(const uint32_t*)(p + 8 * LDT);
                af[im][2] = *(const uint32_t*)(p + 8);
                af[im][3] = *(const uint32_t*)(p + 8 * LDT + 8);
            }
            #pragma unroll
            for (int in = 0; in < 4; in++) {
                int c = wn * 32 + in * 8 + g;
                const bf16* p = Ws + c * LDT + kk + tg * 2;
                bf[in][0] = *(const uint32_t*)p;
                bf[in][1] = *(const uint32_t*)(p + 8);
            }
            #pragma unroll
            for (int im = 0; im < 4; im++)
                #pragma unroll
                for (int in = 0; in < 4; in++)
                    mma16816(acc[im][in], af[im], bf[in]);
        }
        __syncthreads();
    }

    // epilogue
    #pragma unroll
    for (int im = 0; im < 4; im++) {
        int r0 = m0 + wm * 64 + im * 16 + g;
        #pragma unroll
        for (int in = 0; in < 4; in++) {
            int c = n0 + wn * 32 + in * 8 + tg * 2;
            float b0 = bias[c], b1 = bias[c + 1];
            float v00 = acc[im][in][0] + b0, v01 = acc[im][in][1] + b1;
            float v10 = acc[im][in][2] + b0, v11 = acc[im][in][3] + b1;
            if (SILU) {
                v00 = v00 / (1.f + expf(-v00)); v01 = v01 / (1.f + expf(-v01));
                v10 = v10 / (1.f + expf(-v10)); v11 = v11 / (1.f + expf(-v11));
            }
            if (RES) {
                float s0 = scale[c], s1 = scale[c + 1];
                float2 ra = *(const float2*)&res[(size_t)r0 * N + c];
                float2 rb = *(const float2*)&res[(size_t)(r0 + 8) * N + c];
                v00 = ra.x + v00 * s0; v01 = ra.y + v01 * s1;
                v10 = rb.x + v10 * s0; v11 = rb.y + v11 * s1;
            }
            if (sizeof(OutT) == 4) {
                *(float2*)((float*)C + (size_t)r0 * N + c) = make_float2(v00, v01);
                *(float2*)((float*)C + (size_t)(r0 + 8) * N + c) = make_float2(v10, v11);
            } else {
                *(bf162*)((bf16*)C + (size_t)r0 * N + c) = __floats2bfloat162_rn(v00, v01);
                *(bf162*)((bf16*)C + (size_t)(r0 + 8) * N + c) = __floats2bfloat162_rn(v10, v11);
            }
        }
    }
}

// per-token LayerNorm over D then elu+1 (in place), warp per token
__global__ void __launch_bounds__(256) k_lnelu(float* __restrict__ X,
        const float* __restrict__ gam, const float* __restrict__ bet) {
    int warp = threadIdx.x >> 5, lane = threadIdx.x & 31;
    int t = blockIdx.x * 8 + warp;
    size_t base = (size_t)t * D;
    float v[12];
    float s = 0.f, s2 = 0.f;
    #pragma unroll
    for (int j = 0; j < 12; j++) {
        v[j] = X[base + j * 32 + lane];
        s += v[j]; s2 += v[j] * v[j];
    }
    #pragma unroll
    for (int o = 16; o >= 1; o >>= 1) {
        s  += __shfl_xor_sync(0xffffffff, s, o);
        s2 += __shfl_xor_sync(0xffffffff, s2, o);
    }
    float mean = s / (float)D;
    float var = s2 / (float)D - mean * mean;
    float rstd = rsqrtf(var + 1e-5f);
    #pragma unroll
    for (int j = 0; j < 12; j++) {
        int d = j * 32 + lane;
        float y = (v[j] - mean) * rstd * gam[d] + bet[d];
        X[base + d] = (y > 0.f) ? (y + 1.f) : expf(y);
    }
}

// kv[bh] = sum_i k_i outer v_i ; ksum[bh] = sum_i k_i
__global__ void __launch_bounds__(256) k_attn_kv(const float* __restrict__ k,
                                                 const float* __restrict__ v,
                                                 float* __restrict__ kv,
                                                 float* __restrict__ ksum) {
    int bh = blockIdx.x;
    int h = bh & (NH - 1), bc = bh >> 3;
    __shared__ float sk[16][HD];
    __shared__ float sv[16][HD];
    int tid = threadIdx.x;
    float acc[9];
    #pragma unroll
    for (int p = 0; p < 9; p++) acc[p] = 0.f;
    float ks = 0.f;
    int base = tid * 9;
    int dp[9], ep[9];
    #pragma unroll
    for (int p = 0; p < 9; p++) { dp[p] = (base + p) / HD; ep[p] = (base + p) % HD; }

    for (int c = 0; c < GS / 16; c++) {
        int tt0 = bc * GS + c * 16;
        #pragma unroll
        for (int r = 0; r < 3; r++) {
            int j = r * 256 + tid;
            int ti = j / HD, d = j % HD;
            size_t src = (size_t)(tt0 + ti) * D + h * HD + d;
            sk[ti][d] = k[src];
            sv[ti][d] = v[src];
        }
        __syncthreads();
        #pragma unroll 4
        for (int ti = 0; ti < 16; ti++) {
            #pragma unroll
            for (int p = 0; p < 9; p++) acc[p] += sk[ti][dp[p]] * sv[ti][ep[p]];
        }
        if (tid < HD) {
            #pragma unroll 4
            for (int ti = 0; ti < 16; ti++) ks += sk[ti][tid];
        }
        __syncthreads();
    }
    #pragma unroll
    for (int p = 0; p < 9; p++) kv[(size_t)bh * HD * HD + base + p] = acc[p];
    if (tid < HD) ksum[bh * HD + tid] = ks;
}

// out[t,h,e] = (q . kv[:,e]) / (q . ksum + 1e-8), bf16 output
__global__ void __launch_bounds__(256) k_attn_apply(const float* __restrict__ q,
                                                    const float* __restrict__ kv,
                                                    const float* __restrict__ ksum,
                                                    bf16* __restrict__ out) {
    int bh = blockIdx.x;
    int tile = blockIdx.y;
    int h = bh & (NH - 1), bc = bh >> 3;
    __shared__ float skv[HD * HD];
    __shared__ float sks[HD];
    __shared__ float sq[16][HD];
    int tid = threadIdx.x;
    for (int i = tid; i < HD * HD; i += 256) skv[i] = kv[(size_t)bh * HD * HD + i];
    if (tid < HD) sks[tid] = ksum[bh * HD + tid];
    __syncthreads();
    int t0 = bc * GS + tile * 64;
    for (int sub = 0; sub < 4; sub++) {
        int tt0 = t0 + sub * 16;
        #pragma unroll
        for (int r = 0; r < 3; r++) {
            int j = r * 256 + tid;
            int ti = j / HD, d = j % HD;
            sq[ti][d] = q[(size_t)(tt0 + ti) * D + h * HD + d];
        }
        __syncthreads();
        #pragma unroll
        for (int r = 0; r < 3; r++) {
            int j = r * 256 + tid;
            int ti = j / HD, e = j % HD;
            float num = 0.f, den = 0.f;
            #pragma unroll
            for (int d = 0; d < HD; d++) {
                float qq = sq[ti][d];
                num += qq * skv[d * HD + e];
                den += qq * sks[d];
            }
            out[(size_t)(tt0 + ti) * D + h * HD + e] = __float2bfloat16(num / (den + 1e-8f));
        }
        __syncthreads();
    }
}

__global__ void k_gx2part(const float* __restrict__ wi, float* __restrict__ part) {
    int b = blockIdx.x, dbase = blockIdx.y * 128, slice = blockIdx.z;
    int d = dbase + threadIdx.x;
    float s = 0.f;
    int t0 = slice * 256;
    for (int t = 0; t < 256; t++) {
        float v = wi[(size_t)(b * NP + t0 + t) * D + d];
        s += v * v;
    }
    part[(size_t)(b * 16 + slice) * D + d] = s;
}

__global__ void k_gx2red(const float* __restrict__ part, float* __restrict__ gx2) {
    int b = blockIdx.x, d = blockIdx.y * 128 + threadIdx.x;
    float s = 0.f;
    #pragma unroll
    for (int sl = 0; sl < 16; sl++) s += part[(size_t)(b * 16 + sl) * D + d];
    gx2[b * D + d] = sqrtf(s);
}

// x2 = A2[b,d]*wi + C2[b,d], bf16 output
__global__ void k_x2(const float* __restrict__ wi, const float* __restrict__ A,
                     const float* __restrict__ C, bf16* __restrict__ x2) {
    size_t idx = (size_t)blockIdx.x * 256 + threadIdx.x;
    int t = (int)(idx / D), d = (int)(idx % D);
    int b = t >> 12;
    x2[idx] = __float2bfloat16(A[b * D + d] * wi[idx] + C[b * D + d]);
}

// out[b,d,pix] = image[b,d,pix] + wif[token(pix), d] * final_scalar[d]  (transpose)
__global__ void __launch_bounds__(256) k_final_t(
        const float* __restrict__ img, const float* __restrict__ wif,
        const int* __restrict__ invp, const float* __restrict__ fs,
        float* __restrict__ out) {
    __shared__ float tile[64][65];
    __shared__ int sinv[64];
    int p0 = blockIdx.x * 64, d0 = blockIdx.y * 64, b = blockIdx.z;
    int tid = threadIdx.x;
    if (tid < 64) sinv[tid] = invp[p0 + tid];
    __syncthreads();
    #pragma unroll
    for (int l = 0; l < 4; l++) {
        int j = tid + l * 256;
        int jp = j >> 4, i4 = (j & 15) * 4;
        int t = sinv[jp];
        float4 v = *(const float4*)(wif + ((size_t)(b * NP + t)) * D + d0 + i4);
        tile[i4 + 0][jp] = v.x; tile[i4 + 1][jp] = v.y;
        tile[i4 + 2][jp] = v.z; tile[i4 + 3][jp] = v.w;
    }
    __syncthreads();
    #pragma unroll
    for (int l = 0; l < 4; l++) {
        int j = tid + l * 256;
        int i = j >> 4, q = (j & 15) * 4;
        size_t o = ((size_t)(b * D + d0 + i)) * NP + p0 + q;
        float4 im4 = *(const float4*)(img + o);
        float f = fs[d0 + i];
        float4 r;
        r.x = im4.x + tile[i][q + 0] * f;
        r.y = im4.y + tile[i][q + 1] * f;
        r.z = im4.z + tile[i][q + 2] * f;
        r.w = im4.w + tile[i][q + 3] * f;
        *(float4*)(out + o) = r;
    }
}

// ---------------- driver ----------------------------------------------------
extern "C" void kernel_launch(void* const* d_in, const int* in_sizes, int n_in,
                              void* d_out, int out_size) {
    const float* image  = (const float*)d_in[0];
    const float* film   = (const float*)d_in[1];
    const int*   perm   = (const int*)d_in[2];
    const float* Wq = (const float*)d_in[3];  const float* bq = (const float*)d_in[4];
    const float* Wk = (const float*)d_in[5];  const float* bk = (const float*)d_in[6];
    const float* Wv = (const float*)d_in[7];  const float* bv = (const float*)d_in[8];
    const float* Wo = (const float*)d_in[9];  const float* bo = (const float*)d_in[10];
    const float* lnq_g = (const float*)d_in[11]; const float* lnq_b = (const float*)d_in[12];
    const float* lnk_g = (const float*)d_in[13]; const float* lnk_b = (const float*)d_in[14];
    const float* ada1_W = (const float*)d_in[15]; const float* ada1_b = (const float*)d_in[16];
    const float* grn1_g = (const float*)d_in[17]; const float* grn1_b = (const float*)d_in[18];
    const float* ada2_W = (const float*)d_in[19]; const float* ada2_b = (const float*)d_in[20];
    const float* grn2_g = (const float*)d_in[21]; const float* grn2_b = (const float*)d_in[22];
    const float* conv1_W = (const float*)d_in[23]; const float* conv1_b = (const float*)d_in[24];
    const float* conv2_W = (const float*)d_in[25]; const float* conv2_b = (const float*)d_in[26];
    const float* cs  = (const float*)d_in[27];
    const float* ffs = (const float*)d_in[28];
    const float* fs  = (const float*)d_in[29];
    float* out = (float*)d_out;

    float *p_gb1, *p_gb2, *p_gx, *p_gm, *p_A1, *p_C1, *p_A2, *p_C2, *p_gx2, *p_part;
    int* p_invp;
    float *p_imtok, *p_q, *p_k, *p_v, *p_wi, *p_wif, *p_kv, *p_ks;
    bf16 *p_xg16, *p_att16, *p_x216, *p_h116;
    bf16 *p_wq16, *p_wk16, *p_wv16, *p_wo16, *p_c1w16, *p_c2w16;
    cudaGetSymbolAddress((void**)&p_gb1, g_gb1);
    cudaGetSymbolAddress((void**)&p_gb2, g_gb2);
    cudaGetSymbolAddress((void**)&p_gx, g_gx);
    cudaGetSymbolAddress((void**)&p_gm, g_gm);
    cudaGetSymbolAddress((void**)&p_A1, g_A1);
    cudaGetSymbolAddress((void**)&p_C1, g_C1);
    cudaGetSymbolAddress((void**)&p_A2, g_A2);
    cudaGetSymbolAddress((void**)&p_C2, g_C2);
    cudaGetSymbolAddress((void**)&p_gx2, g_gx2);
    cudaGetSymbolAddress((void**)&p_part, g_part);
    cudaGetSymbolAddress((void**)&p_invp, g_invp);
    cudaGetSymbolAddress((void**)&p_imtok, g_imtok);
    cudaGetSymbolAddress((void**)&p_q, g_q);
    cudaGetSymbolAddress((void**)&p_k, g_k);
    cudaGetSymbolAddress((void**)&p_v, g_v);
    cudaGetSymbolAddress((void**)&p_wi, g_wi);
    cudaGetSymbolAddress((void**)&p_wif, g_wif);
    cudaGetSymbolAddress((void**)&p_kv, g_kv);
    cudaGetSymbolAddress((void**)&p_ks, g_ks);
    cudaGetSymbolAddress((void**)&p_xg16, g_xg16);
    cudaGetSymbolAddress((void**)&p_att16, g_att16);
    cudaGetSymbolAddress((void**)&p_x216, g_x216);
    cudaGetSymbolAddress((void**)&p_h116, g_h116);
    cudaGetSymbolAddress((void**)&p_wq16, g_wq16);
    cudaGetSymbolAddress((void**)&p_wk16, g_wk16);
    cudaGetSymbolAddress((void**)&p_wv16, g_wv16);
    cudaGetSymbolAddress((void**)&p_wo16, g_wo16);
    cudaGetSymbolAddress((void**)&p_c1w16, g_c1w16);
    cudaGetSymbolAddress((void**)&p_c2w16, g_c2w16);

    // weight conversions (cheap)
    k_cvt<<<(D*D + 255)/256, 256>>>(Wq, p_wq16, D*D);
    k_cvt<<<(D*D + 255)/256, 256>>>(Wk, p_wk16, D*D);
    k_cvt<<<(D*D + 255)/256, 256>>>(Wv, p_wv16, D*D);
    k_cvt<<<(D*D + 255)/256, 256>>>(Wo, p_wo16, D*D);
    k_cvt<<<(D4*D + 255)/256, 256>>>(conv1_W, p_c1w16, D4*D);
    k_cvt<<<(D*D4 + 255)/256, 256>>>(conv2_W, p_c2w16, D*D4);

    k_invperm<<<16, 256>>>(perm, p_invp);
    k_film<<<48, 256>>>(film, ada1_W, ada1_b, ada2_W, ada2_b, p_gb1, p_gb2);
    k_gx_img<<<B * D, 256>>>(image, p_gx);
    k_gmean<<<B, 384>>>(p_gx, p_gm);
    k_coef<<<(B * D + 255) / 256, 256>>>(p_gx, p_gm, grn1_g, grn1_b, p_gb1, p_A1, p_C1);
    k_gather_t<<<dim3(NP/64, D/64, B), 256>>>(image, p_invp, p_A1, p_C1, p_imtok, p_xg16);

    gemm_mma<float,false,false><<<dim3(3, 256), 256>>>(p_xg16, p_wq16, bq, nullptr, nullptr, p_q, T, D, D);
    gemm_mma<float,false,false><<<dim3(3, 256), 256>>>(p_xg16, p_wk16, bk, nullptr, nullptr, p_k, T, D, D);
    gemm_mma<float,false,false><<<dim3(3, 256), 256>>>(p_xg16, p_wv16, bv, nullptr, nullptr, p_v, T, D, D);

    k_lnelu<<<T/8, 256>>>(p_q, lnq_g, lnq_b);
    k_lnelu<<<T/8, 256>>>(p_k, lnk_g, lnk_b);

    k_attn_kv<<<B * NC * NH, 256>>>(p_k, p_v, p_kv, p_ks);
    k_attn_apply<<<dim3(B * NC * NH, 16), 256>>>(p_q, p_kv, p_ks, p_att16);

    // wi = imtok + (attn@Wo^T + bo) * cs   (fused epilogue)
    gemm_mma<float,false,true><<<dim3(3, 256), 256>>>(p_att16, p_wo16, bo, p_imtok, cs, p_wi, T, D, D);

    k_gx2part<<<dim3(B, 3, 16), 128>>>(p_wi, p_part);
    k_gx2red<<<dim3(B, 3), 128>>>(p_part, p_gx2);
    k_gmean<<<B, 384>>>(p_gx2, p_gm);
    k_coef<<<(B * D + 255) / 256, 256>>>(p_gx2, p_gm, grn2_g, grn2_b, p_gb2, p_A2, p_C2);
    k_x2<<<(int)(((size_t)T*D) / 256), 256>>>(p_wi, p_A2, p_C2, p_x216);

    // h1 = silu(x2 @ conv1^T + b1)
    gemm_mma<bf16,true,false><<<dim3(12, 256), 256>>>(p_x216, p_c1w16, conv1_b, nullptr, nullptr, p_h116, T, D4, D);
    // wif = wi + (h1 @ conv2^T + b2) * ffs
    gemm_mma<float,false,true><<<dim3(3, 256), 256>>>(p_h116, p_c2w16, conv2_b, p_wi, ffs, p_wif, T, D, D4);

    k_final_t<<<dim3(NP/64, D/64, B), 256>>>(image, p_wif, p_invp, fs, out);
}

// round 3
// speedup vs baseline: 3.6790x; 1.0587x over previous
#include <cuda_runtime.h>
#include <cuda_bf16.h>
#include <math.h>
#include <stdint.h>

#define B   8
#define D   384
#define FD  256
#define NP  4096
#define NH  8
#define NC  4
#define HD  48
#define GS  1024
#define T   (B*NP)     /* 32768 tokens */
#define D4  1536
#define D2  768
#define QS  1152       /* packed qkv row stride */

typedef __nv_bfloat16 bf16;
typedef __nv_bfloat162 bf162;

// ---------------- scratch (device globals) ----------------------------------
static __device__ float g_gb1[B*D2];
static __device__ float g_gb2[B*D2];
static __device__ float g_gx[B*D];
static __device__ float g_gm[B];
static __device__ float g_A1[B*D];
static __device__ float g_C1[B*D];
static __device__ float g_A2[B*D];
static __device__ float g_C2[B*D];
static __device__ float g_gx2sq[B*D];
static __device__ int   g_invp[NP];
static __device__ float g_imtok[(size_t)T*D];
static __device__ float g_qkv[(size_t)T*QS];
static __device__ float g_wi[(size_t)T*D];
static __device__ float g_wif[(size_t)T*D];
static __device__ float g_kv[B*NC*NH*HD*HD];
static __device__ float g_ks[B*NC*NH*HD];
static __device__ float g_bqkv[QS];
// bf16 activations
static __device__ bf16  g_xg16[(size_t)T*D];
static __device__ bf16  g_att16[(size_t)T*D];
static __device__ bf16  g_x216[(size_t)T*D];
static __device__ bf16  g_h116[(size_t)T*D4];
// bf16 weights
static __device__ bf16  g_wqkv16[QS*D];
static __device__ bf16  g_wo16[D*D];
static __device__ bf16  g_c1w16[D4*D];
static __device__ bf16  g_c2w16[D*D4];

// ---------------- helpers ----------------------------------------------------
__device__ __forceinline__ uint32_t sptr(const void* p) {
    return (uint32_t)__cvta_generic_to_shared(p);
}
__device__ __forceinline__ void cp16(void* s, const void* g) {
    asm volatile("cp.async.cg.shared.global [%0], [%1], 16;\n"
                 :: "r"(sptr(s)), "l"(g));
}
__device__ __forceinline__ void cp_commit() {
    asm volatile("cp.async.commit_group;\n");
}
template<int N>
__device__ __forceinline__ void cp_wait() {
    asm volatile("cp.async.wait_group %0;\n" :: "n"(N));
}
__device__ __forceinline__ void mma16816(float* c, const uint32_t* a, const uint32_t* b) {
    asm volatile(
        "mma.sync.aligned.m16n8k16.row.col.f32.bf16.bf16.f32 "
        "{%0,%1,%2,%3}, {%4,%5,%6,%7}, {%8,%9}, {%0,%1,%2,%3};\n"
        : "+f"(c[0]), "+f"(c[1]), "+f"(c[2]), "+f"(c[3])
        : "r"(a[0]), "r"(a[1]), "r"(a[2]), "r"(a[3]), "r"(b[0]), "r"(b[1]));
}

__device__ __forceinline__ float blockReduce384(float v, float* sdata) {
    int tid = threadIdx.x;
    sdata[tid] = v;
    if (tid < 128) sdata[384 + tid] = 0.f;
    __syncthreads();
    #pragma unroll
    for (int s = 256; s >= 1; s >>= 1) {
        if (tid < s) sdata[tid] += sdata[tid + s];
        __syncthreads();
    }
    float r = sdata[0];
    __syncthreads();
    return r;
}

// ---------------- small kernels ----------------------------------------------
__global__ void k_invperm(const int* __restrict__ perm, int* __restrict__ invp) {
    int i = blockIdx.x * blockDim.x + threadIdx.x;
    if (i < NP) invp[perm[i]] = i;
}

__global__ void k_cvt(const float* __restrict__ src, bf16* __restrict__ dst, int n) {
    int i = blockIdx.x * blockDim.x + threadIdx.x;
    if (i < n) dst[i] = __float2bfloat16(src[i]);
}

__global__ void k_zero(float* __restrict__ p, int n) {
    int i = blockIdx.x * blockDim.x + threadIdx.x;
    if (i < n) p[i] = 0.f;
}

__global__ void k_catbias(const float* __restrict__ a, const float* __restrict__ b,
                          const float* __restrict__ c, float* __restrict__ o) {
    int i = blockIdx.x * blockDim.x + threadIdx.x;
    if (i < D) { o[i] = a[i]; o[D + i] = b[i]; o[2 * D + i] = c[i]; }
}

__global__ void k_film(const float* __restrict__ film,
                       const float* __restrict__ W1, const float* __restrict__ b1,
                       const float* __restrict__ W2, const float* __restrict__ b2,
                       float* __restrict__ gb1, float* __restrict__ gb2) {
    int o = blockIdx.x * blockDim.x + threadIdx.x;
    if (o >= 2 * B * D2) return;
    int which = o / (B * D2);
    int r = o % (B * D2);
    int b = r / D2, j = r % D2;
    const float* W = which ? W2 : W1;
    const float* bb = which ? b2 : b1;
    const float* f = film + b * FD;
    const float* w = W + (size_t)j * FD;
    float s = 0.f;
    #pragma unroll 8
    for (int i = 0; i < FD; i++) s += f[i] * w[i];
    s += bb[j];
    if (which) gb2[r] = s; else gb1[r] = s;
}

__global__ void k_gx_img(const float* __restrict__ img, float* __restrict__ gx) {
    __shared__ float sdata[256];
    int bd = blockIdx.x;
    const float* p = img + (size_t)bd * NP;
    float s = 0.f;
    for (int i = threadIdx.x; i < NP; i += 256) { float v = p[i]; s += v * v; }
    sdata[threadIdx.x] = s; __syncthreads();
    for (int st = 128; st >= 1; st >>= 1) {
        if (threadIdx.x < st) sdata[threadIdx.x] += sdata[threadIdx.x + st];
        __syncthreads();
    }
    if (threadIdx.x == 0) gx[bd] = sqrtf(sdata[0]);
}

// gm[b] = mean_d of (dosqrt? sqrt(gx) : gx)
__global__ void k_gmean(const float* __restrict__ gx, float* __restrict__ gm, int dosqrt) {
    __shared__ float sdata[512];
    int b = blockIdx.x;
    float v = gx[b * D + threadIdx.x];
    if (dosqrt) v = sqrtf(v);
    float s = blockReduce384(v, sdata);
    if (threadIdx.x == 0) gm[b] = s / (float)D;
}

__global__ void k_coef(const float* __restrict__ gx, const float* __restrict__ gm,
                       const float* __restrict__ gg, const float* __restrict__ gb_,
                       const float* __restrict__ gbmat,
                       float* __restrict__ A, float* __restrict__ C, int dosqrt) {
    int idx = blockIdx.x * blockDim.x + threadIdx.x;
    if (idx >= B * D) return;
    int b = idx / D, d = idx % D;
    float gv = gx[idx];
    if (dosqrt) gv = sqrtf(gv);
    float nx = gv / (gm[b] + 1e-6f);
    float gamma = gbmat[b * D2 + d];
    float beta  = gbmat[b * D2 + D + d];
    A[idx] = ((1.f + gg[d]) * nx + 1.f) * (1.f + gamma);
    C[idx] = gb_[d] * (1.f + gamma) + beta;
}

// transpose-gather: image [b,d,pix] -> token-major imtok fp32 + xg bf16 (adaln applied)
__global__ void __launch_bounds__(256) k_gather_t(
        const float* __restrict__ img, const int* __restrict__ invp,
        const float* __restrict__ A, const float* __restrict__ C,
        float* __restrict__ imtok, bf16* __restrict__ xg) {
    __shared__ float tile[64][65];
    __shared__ int sinv[64];
    int p0 = blockIdx.x * 64, d0 = blockIdx.y * 64, b = blockIdx.z;
    int tid = threadIdx.x;
    if (tid < 64) sinv[tid] = invp[p0 + tid];
    #pragma unroll
    for (int l = 0; l < 4; l++) {
        int j = tid + l * 256;
        int i = j >> 4, q = (j & 15) * 4;
        float4 v = *(const float4*)(img + ((size_t)(b * D + d0 + i)) * NP + p0 + q);
        tile[i][q + 0] = v.x; tile[i][q + 1] = v.y;
        tile[i][q + 2] = v.z; tile[i][q + 3] = v.w;
    }
    __syncthreads();
    #pragma unroll
    for (int l = 0; l < 4; l++) {
        int j = tid + l * 256;
        int jp = j >> 4, i4 = (j & 15) * 4;
        int t = sinv[jp];
        size_t o = ((size_t)(b * NP + t)) * D + d0 + i4;
        float vv[4], xv[4];
        #pragma unroll
        for (int r = 0; r < 4; r++) {
            vv[r] = tile[i4 + r][jp];
            int cidx = b * D + d0 + i4 + r;
            xv[r] = A[cidx] * vv[r] + C[cidx];
        }
        *(float4*)&imtok[o] = make_float4(vv[0], vv[1], vv[2], vv[3]);
        *(bf162*)&xg[o] = __floats2bfloat162_rn(xv[0], xv[1]);
        *(bf162*)&xg[o + 2] = __floats2bfloat162_rn(xv[2], xv[3]);
    }
}

// ---------------- bf16 tensor-core GEMM: C = act(A @ W^T + bias) [+res*scale] -
// A: [M,K] bf16 row-major, W: [N,K] bf16 row-major. BM=BN=128, BK=32, 3 stages.
#define LDT 40
#define STG 3
#define GEMM_SMEM (STG * 2 * 128 * LDT * 2)
template<typename OutT, bool SILU, bool RES, bool GX2>
__global__ void __launch_bounds__(256, 2) gemm_mma(
        const bf16* __restrict__ A, const bf16* __restrict__ W,
        const float* __restrict__ bias, const float* __restrict__ res,
        const float* __restrict__ scale, OutT* __restrict__ C,
        float* __restrict__ gx2sq, int M, int N, int K) {
    extern __shared__ bf16 smem[];
    bf16* sA = smem;                    // [STG][128*LDT]
    bf16* sW = smem + STG * 128 * LDT;  // [STG][128*LDT]
    int tid = threadIdx.x;
    int m0 = blockIdx.y * 128, n0 = blockIdx.x * 128;
    int lane = tid & 31, warp = tid >> 5;
    int g = lane >> 2, tg = lane & 3;
    int wm = warp >> 2, wn = warp & 3;

    float acc[4][4][4];
    #pragma unroll
    for (int i = 0; i < 4; i++)
        #pragma unroll
        for (int j = 0; j < 4; j++)
            #pragma unroll
            for (int p = 0; p < 4; p++) acc[i][j][p] = 0.f;

    int nt = K / 32;
    auto issue = [&](int t) {
        if (t < nt) {
            int s = t % STG;
            int k0 = t * 32;
            #pragma unroll
            for (int l = 0; l < 2; l++) {
                int j = tid + l * 256;
                int row = j >> 2, q = (j & 3) * 8;
                cp16(&sA[s * 128 * LDT + row * LDT + q], A + (size_t)(m0 + row) * K + k0 + q);
                cp16(&sW[s * 128 * LDT + row * LDT + q], W + (size_t)(n0 + row) * K + k0 + q);
            }
        }
        cp_commit();   // always commit (possibly empty) to keep group counts exact
    };

    issue(0);
    issue(1);
    for (int t = 0; t < nt; t++) {
        cp_wait<STG - 2>();
        __syncthreads();
        int s = t % STG;
        const bf16* As = sA + s * 128 * LDT;
        const bf16* Ws = sW + s * 128 * LDT;
        #pragma unroll
        for (int kk = 0; kk < 32; kk += 16) {
            uint32_t af[4][4], bfr[4][2];
            #pragma unroll
            for (int im = 0; im < 4; im++) {
                int r = wm * 64 + im * 16 + g;
                const bf16* p = As + r * LDT + kk + tg * 2;
                af[im][0] = *(const uint32_t*)p;
                af[im][1] = *(const uint32_t*)(p + 8 * LDT);
                af[im][2] = *(const uint32_t*)(p + 8);
                af[im][3] = *(const uint32_t*)(p + 8 * LDT + 8);
            }
            #pragma unroll
            for (int in = 0; in < 4; in++) {
                int c = wn * 32 + in * 8 + g;
                const bf16* p = Ws + c * LDT + kk + tg * 2;
                bfr[in][0] = *(const uint32_t*)p;
                bfr[in][1] = *(const uint32_t*)(p + 8);
            }
            #pragma unroll
            for (int im = 0; im < 4; im++)
                #pragma unroll
                for (int in = 0; in < 4; in++)
                    mma16816(acc[im][in], af[im], bfr[in]);
        }
        __syncthreads();
        issue(t + 2);
    }

    // epilogue
    float sums[4][2];
    if (GX2) {
        #pragma unroll
        for (int in = 0; in < 4; in++) { sums[in][0] = 0.f; sums[in][1] = 0.f; }
    }
    #pragma unroll
    for (int im = 0; im < 4; im++) {
        int r0 = m0 + wm * 64 + im * 16 + g;
        #pragma unroll
        for (int in = 0; in < 4; in++) {
            int c = n0 + wn * 32 + in * 8 + tg * 2;
            float b0 = bias[c], b1 = bias[c + 1];
            float v00 = acc[im][in][0] + b0, v01 = acc[im][in][1] + b1;
            float v10 = acc[im][in][2] + b0, v11 = acc[im][in][3] + b1;
            if (SILU) {
                v00 = v00 / (1.f + expf(-v00)); v01 = v01 / (1.f + expf(-v01));
                v10 = v10 / (1.f + expf(-v10)); v11 = v11 / (1.f + expf(-v11));
            }
            if (RES) {
                float s0 = scale[c], s1 = scale[c + 1];
                float2 ra = *(const float2*)&res[(size_t)r0 * N + c];
                float2 rb = *(const float2*)&res[(size_t)(r0 + 8) * N + c];
                v00 = ra.x + v00 * s0; v01 = ra.y + v01 * s1;
                v10 = rb.x + v10 * s0; v11 = rb.y + v11 * s1;
            }
            if (GX2) {
                sums[in][0] += v00 * v00 + v10 * v10;
                sums[in][1] += v01 * v01 + v11 * v11;
            }
            if (sizeof(OutT) == 4) {
                *(float2*)((float*)C + (size_t)r0 * N + c) = make_float2(v00, v01);
                *(float2*)((float*)C + (size_t)(r0 + 8) * N + c) = make_float2(v10, v11);
            } else {
                *(bf162*)((bf16*)C + (size_t)r0 * N + c) = __floats2bfloat162_rn(v00, v01);
                *(bf162*)((bf16*)C + (size_t)(r0 + 8) * N + c) = __floats2bfloat162_rn(v10, v11);
            }
        }
    }
    if (GX2) {
        // reduce over g (8 row-groups) within warp; lanes 0-3 hold column sums
        #pragma unroll
        for (int off = 4; off <= 16; off <<= 1) {
            #pragma unroll
            for (int in = 0; in < 4; in++) {
                sums[in][0] += __shfl_xor_sync(0xffffffff, sums[in][0], off);
                sums[in][1] += __shfl_xor_sync(0xffffffff, sums[in][1], off);
            }
        }
        if (lane < 4) {
            int b = m0 >> 12;  // all 128 rows of this CTA share batch index
            #pragma unroll
            for (int in = 0; in < 4; in++) {
                int c = n0 + wn * 32 + in * 8 + tg * 2;
                atomicAdd(&gx2sq[b * D + c], sums[in][0]);
                atomicAdd(&gx2sq[b * D + c + 1], sums[in][1]);
            }
        }
    }
}

// per-token LayerNorm over D then elu+1 (in place), warp per token; y: 0=q seg, 1=k seg
__global__ void __launch_bounds__(256) k_lnelu(float* __restrict__ X,
        const float* __restrict__ gq, const float* __restrict__ bq_,
        const float* __restrict__ gk, const float* __restrict__ bk_) {
    int warp = threadIdx.x >> 5, lane = threadIdx.x & 31;
    int t = blockIdx.x * 8 + warp;
    int seg = blockIdx.y;
    const float* gam = seg ? gk : gq;
    const float* bet = seg ? bk_ : bq_;
    size_t base = (size_t)t * QS + seg * D;
    float v[12];
    float s = 0.f, s2 = 0.f;
    #pragma unroll
    for (int j = 0; j < 12; j++) {
        v[j] = X[base + j * 32 + lane];
        s += v[j]; s2 += v[j] * v[j];
    }
    #pragma unroll
    for (int o = 16; o >= 1; o >>= 1) {
        s  += __shfl_xor_sync(0xffffffff, s, o);
        s2 += __shfl_xor_sync(0xffffffff, s2, o);
    }
    float mean = s / (float)D;
    float var = s2 / (float)D - mean * mean;
    float rstd = rsqrtf(var + 1e-5f);
    #pragma unroll
    for (int j = 0; j < 12; j++) {
        int d = j * 32 + lane;
        float y = (v[j] - mean) * rstd * gam[d] + bet[d];
        X[base + d] = (y > 0.f) ? (y + 1.f) : expf(y);
    }
}

// kv[bh] = sum_i k_i outer v_i ; ksum[bh] = sum_i k_i   (qkv packed, stride QS)
__global__ void __launch_bounds__(256) k_attn_kv(const float* __restrict__ qkv,
                                                 float* __restrict__ kv,
                                                 float* __restrict__ ksum) {
    int bh = blockIdx.x;
    int h = bh & (NH - 1), bc = bh >> 3;
    __shared__ float sk[16][HD];
    __shared__ float sv[16][HD];
    int tid = threadIdx.x;
    float acc[9];
    #pragma unroll
    for (int p = 0; p < 9; p++) acc[p] = 0.f;
    float ks = 0.f;
    int base = tid * 9;
    int dp[9], ep[9];
    #pragma unroll
    for (int p = 0; p < 9; p++) { dp[p] = (base + p) / HD; ep[p] = (base + p) % HD; }

    for (int c = 0; c < GS / 16; c++) {
        int tt0 = bc * GS + c * 16;
        #pragma unroll
        for (int r = 0; r < 3; r++) {
            int j = r * 256 + tid;
            int ti = j / HD, d = j % HD;
            size_t row = (size_t)(tt0 + ti) * QS + h * HD + d;
            sk[ti][d] = qkv[row + D];
            sv[ti][d] = qkv[row + 2 * D];
        }
        __syncthreads();
        #pragma unroll 4
        for (int ti = 0; ti < 16; ti++) {
            #pragma unroll
            for (int p = 0; p < 9; p++) acc[p] += sk[ti][dp[p]] * sv[ti][ep[p]];
        }
        if (tid < HD) {
            #pragma unroll 4
            for (int ti = 0; ti < 16; ti++) ks += sk[ti][tid];
        }
        __syncthreads();
    }
    #pragma unroll
    for (int p = 0; p < 9; p++) kv[(size_t)bh * HD * HD + base + p] = acc[p];
    if (tid < HD) ksum[bh * HD + tid] = ks;
}

// out[t,h,e] = (q . kv[:,e]) / (q . ksum + 1e-8), bf16 output
__global__ void __launch_bounds__(256) k_attn_apply(const float* __restrict__ qkv,
                                                    const float* __restrict__ kv,
                                                    const float* __restrict__ ksum,
                                                    bf16* __restrict__ out) {
    int bh = blockIdx.x;
    int tile = blockIdx.y;
    int h = bh & (NH - 1), bc = bh >> 3;
    __shared__ float skv[HD * HD];
    __shared__ float sks[HD];
    __shared__ float sq[16][HD];
    int tid = threadIdx.x;
    for (int i = tid; i < HD * HD; i += 256) skv[i] = kv[(size_t)bh * HD * HD + i];
    if (tid < HD) sks[tid] = ksum[bh * HD + tid];
    __syncthreads();
    int t0 = bc * GS + tile * 64;
    for (int sub = 0; sub < 4; sub++) {
        int tt0 = t0 + sub * 16;
        #pragma unroll
        for (int r = 0; r < 3; r++) {
            int j = r * 256 + tid;
            int ti = j / HD, d = j % HD;
            sq[ti][d] = qkv[(size_t)(tt0 + ti) * QS + h * HD + d];
        }
        __syncthreads();
        #pragma unroll
        for (int r = 0; r < 3; r++) {
            int j = r * 256 + tid;
            int ti = j / HD, e = j % HD;
            float num = 0.f, den = 0.f;
            #pragma unroll
            for (int d = 0; d < HD; d++) {
                float qq = sq[ti][d];
                num += qq * skv[d * HD + e];
                den += qq * sks[d];
            }
            out[(size_t)(tt0 + ti) * D + h * HD + e] = __float2bfloat16(num / (den + 1e-8f));
        }
        __syncthreads();
    }
}

// x2 = A2[b,d]*wi + C2[b,d], bf16 output
__global__ void k_x2(const float* __restrict__ wi, const float* __restrict__ A,
                     const float* __restrict__ C, bf16* __restrict__ x2) {
    size_t idx = (size_t)blockIdx.x * 256 + threadIdx.x;
    int t = (int)(idx / D), d = (int)(idx % D);
    int b = t >> 12;
    x2[idx] = __float2bfloat16(A[b * D + d] * wi[idx] + C[b * D + d]);
}

// out[b,d,pix] = image[b,d,pix] + wif[token(pix), d] * final_scalar[d]  (transpose)
__global__ void __launch_bounds__(256) k_final_t(
        const float* __restrict__ img, const float* __restrict__ wif,
        const int* __restrict__ invp, const float* __restrict__ fs,
        float* __restrict__ out) {
    __shared__ float tile[64][65];
    __shared__ int sinv[64];
    int p0 = blockIdx.x * 64, d0 = blockIdx.y * 64, b = blockIdx.z;
    int tid = threadIdx.x;
    if (tid < 64) sinv[tid] = invp[p0 + tid];
    __syncthreads();
    #pragma unroll
    for (int l = 0; l < 4; l++) {
        int j = tid + l * 256;
        int jp = j >> 4, i4 = (j & 15) * 4;
        int t = sinv[jp];
        float4 v = *(const float4*)(wif + ((size_t)(b * NP + t)) * D + d0 + i4);
        tile[i4 + 0][jp] = v.x; tile[i4 + 1][jp] = v.y;
        tile[i4 + 2][jp] = v.z; tile[i4 + 3][jp] = v.w;
    }
    __syncthreads();
    #pragma unroll
    for (int l = 0; l < 4; l++) {
        int j = tid + l * 256;
        int i = j >> 4, q = (j & 15) * 4;
        size_t o = ((size_t)(b * D + d0 + i)) * NP + p0 + q;
        float4 im4 = *(const float4*)(img + o);
        float f = fs[d0 + i];
        float4 r;
        r.x = im4.x + tile[i][q + 0] * f;
        r.y = im4.y + tile[i][q + 1] * f;
        r.z = im4.z + tile[i][q + 2] * f;
        r.w = im4.w + tile[i][q + 3] * f;
        *(float4*)(out + o) = r;
    }
}

// ---------------- driver ----------------------------------------------------
extern "C" void kernel_launch(void* const* d_in, const int* in_sizes, int n_in,
                              void* d_out, int out_size) {
    const float* image  = (const float*)d_in[0];
    const float* film   = (const float*)d_in[1];
    const int*   perm   = (const int*)d_in[2];
    const float* Wq = (const float*)d_in[3];  const float* bq = (const float*)d_in[4];
    const float* Wk = (const float*)d_in[5];  const float* bk = (const float*)d_in[6];
    const float* Wv = (const float*)d_in[7];  const float* bv = (const float*)d_in[8];
    const float* Wo = (const float*)d_in[9];  const float* bo = (const float*)d_in[10];
    const float* lnq_g = (const float*)d_in[11]; const float* lnq_b = (const float*)d_in[12];
    const float* lnk_g = (const float*)d_in[13]; const float* lnk_b = (const float*)d_in[14];
    const float* ada1_W = (const float*)d_in[15]; const float* ada1_b = (const float*)d_in[16];
    const float* grn1_g = (const float*)d_in[17]; const float* grn1_b = (const float*)d_in[18];
    const float* ada2_W = (const float*)d_in[19]; const float* ada2_b = (const float*)d_in[20];
    const float* grn2_g = (const float*)d_in[21]; const float* grn2_b = (const float*)d_in[22];
    const float* conv1_W = (const float*)d_in[23]; const float* conv1_b = (const float*)d_in[24];
    const float* conv2_W = (const float*)d_in[25]; const float* conv2_b = (const float*)d_in[26];
    const float* cs  = (const float*)d_in[27];
    const float* ffs = (const float*)d_in[28];
    const float* fs  = (const float*)d_in[29];
    float* out = (float*)d_out;

    float *p_gb1, *p_gb2, *p_gx, *p_gm, *p_A1, *p_C1, *p_A2, *p_C2, *p_gx2sq;
    int* p_invp;
    float *p_imtok, *p_qkv, *p_wi, *p_wif, *p_kv, *p_ks, *p_bqkv;
    bf16 *p_xg16, *p_att16, *p_x216, *p_h116;
    bf16 *p_wqkv16, *p_wo16, *p_c1w16, *p_c2w16;
    cudaGetSymbolAddress((void**)&p_gb1, g_gb1);
    cudaGetSymbolAddress((void**)&p_gb2, g_gb2);
    cudaGetSymbolAddress((void**)&p_gx, g_gx);
    cudaGetSymbolAddress((void**)&p_gm, g_gm);
    cudaGetSymbolAddress((void**)&p_A1, g_A1);
    cudaGetSymbolAddress((void**)&p_C1, g_C1);
    cudaGetSymbolAddress((void**)&p_A2, g_A2);
    cudaGetSymbolAddress((void**)&p_C2, g_C2);
    cudaGetSymbolAddress((void**)&p_gx2sq, g_gx2sq);
    cudaGetSymbolAddress((void**)&p_invp, g_invp);
    cudaGetSymbolAddress((void**)&p_imtok, g_imtok);
    cudaGetSymbolAddress((void**)&p_qkv, g_qkv);
    cudaGetSymbolAddress((void**)&p_wi, g_wi);
    cudaGetSymbolAddress((void**)&p_wif, g_wif);
    cudaGetSymbolAddress((void**)&p_kv, g_kv);
    cudaGetSymbolAddress((void**)&p_ks, g_ks);
    cudaGetSymbolAddress((void**)&p_bqkv, g_bqkv);
    cudaGetSymbolAddress((void**)&p_xg16, g_xg16);
    cudaGetSymbolAddress((void**)&p_att16, g_att16);
    cudaGetSymbolAddress((void**)&p_x216, g_x216);
    cudaGetSymbolAddress((void**)&p_h116, g_h116);
    cudaGetSymbolAddress((void**)&p_wqkv16, g_wqkv16);
    cudaGetSymbolAddress((void**)&p_wo16, g_wo16);
    cudaGetSymbolAddress((void**)&p_c1w16, g_c1w16);
    cudaGetSymbolAddress((void**)&p_c2w16, g_c2w16);

    // opt in to >48KB dynamic smem for each GEMM instantiation
    cudaFuncSetAttribute((const void*)gemm_mma<float,false,false,false>,
                         cudaFuncAttributeMaxDynamicSharedMemorySize, GEMM_SMEM);
    cudaFuncSetAttribute((const void*)gemm_mma<float,false,true,true>,
                         cudaFuncAttributeMaxDynamicSharedMemorySize, GEMM_SMEM);
    cudaFuncSetAttribute((const void*)gemm_mma<bf16,true,false,false>,
                         cudaFuncAttributeMaxDynamicSharedMemorySize, GEMM_SMEM);
    cudaFuncSetAttribute((const void*)gemm_mma<float,false,true,false>,
                         cudaFuncAttributeMaxDynamicSharedMemorySize, GEMM_SMEM);

    // weight conversions (cheap)
    k_cvt<<<(D*D + 255)/256, 256>>>(Wq, p_wqkv16, D*D);
    k_cvt<<<(D*D + 255)/256, 256>>>(Wk, p_wqkv16 + D*D, D*D);
    k_cvt<<<(D*D + 255)/256, 256>>>(Wv, p_wqkv16 + 2*D*D, D*D);
    k_cvt<<<(D*D + 255)/256, 256>>>(Wo, p_wo16, D*D);
    k_cvt<<<(D4*D + 255)/256, 256>>>(conv1_W, p_c1w16, D4*D);
    k_cvt<<<(D*D4 + 255)/256, 256>>>(conv2_W, p_c2w16, D*D4);
    k_catbias<<<2, 256>>>(bq, bk, bv, p_bqkv);
    k_zero<<<12, 256>>>(p_gx2sq, B*D);

    k_invperm<<<16, 256>>>(perm, p_invp);
    k_film<<<48, 256>>>(film, ada1_W, ada1_b, ada2_W, ada2_b, p_gb1, p_gb2);
    k_gx_img<<<B * D, 256>>>(image, p_gx);
    k_gmean<<<B, 384>>>(p_gx, p_gm, 0);
    k_coef<<<(B * D + 255) / 256, 256>>>(p_gx, p_gm, grn1_g, grn1_b, p_gb1, p_A1, p_C1, 0);
    k_gather_t<<<dim3(NP/64, D/64, B), 256>>>(image, p_invp, p_A1, p_C1, p_imtok, p_xg16);

    // packed QKV GEMM: [T, 1152]
    gemm_mma<float,false,false,false><<<dim3(QS/128, T/128), 256, GEMM_SMEM>>>(
        p_xg16, p_wqkv16, p_bqkv, nullptr, nullptr, p_qkv, nullptr, T, QS, D);

    k_lnelu<<<dim3(T/8, 2), 256>>>(p_qkv, lnq_g, lnq_b, lnk_g, lnk_b);

    k_attn_kv<<<B * NC * NH, 256>>>(p_qkv, p_kv, p_ks);
    k_attn_apply<<<dim3(B * NC * NH, 16), 256>>>(p_qkv, p_kv, p_ks, p_att16);

    // wi = imtok + (attn@Wo^T + bo) * cs ; also accumulate gx2sq = sum_t wi^2
    gemm_mma<float,false,true,true><<<dim3(3, T/128), 256, GEMM_SMEM>>>(
        p_att16, p_wo16, bo, p_imtok, cs, p_wi, p_gx2sq, T, D, D);

    k_gmean<<<B, 384>>>(p_gx2sq, p_gm, 1);
    k_coef<<<(B * D + 255) / 256, 256>>>(p_gx2sq, p_gm, grn2_g, grn2_b, p_gb2, p_A2, p_C2, 1);
    k_x2<<<(int)(((size_t)T*D) / 256), 256>>>(p_wi, p_A2, p_C2, p_x216);

    // h1 = silu(x2 @ conv1^T + b1)
    gemm_mma<bf16,true,false,false><<<dim3(12, T/128), 256, GEMM_SMEM>>>(
        p_x216, p_c1w16, conv1_b, nullptr, nullptr, p_h116, nullptr, T, D4, D);
    // wif = wi + (h1 @ conv2^T + b2) * ffs
    gemm_mma<float,false,true,false><<<dim3(3, T/128), 256, GEMM_SMEM>>>(
        p_h116, p_c2w16, conv2_b, p_wi, ffs, p_wif, nullptr, T, D, D4);

    k_final_t<<<dim3(NP/64, D/64, B), 256>>>(image, p_wif, p_invp, fs, out);
}

// round 5
// speedup vs baseline: 3.7752x; 1.0261x over previous
#include <cuda_runtime.h>
#include <cuda_bf16.h>
#include <math.h>
#include <stdint.h>

#define B   8
#define D   384
#define FD  256
#define NP  4096
#define NH  8
#define NC  4
#define HD  48
#define GS  1024
#define T   (B*NP)     /* 32768 tokens */
#define D4  1536
#define D2  768
#define QS  1152       /* packed qkv row stride */

typedef __nv_bfloat16 bf16;
typedef __nv_bfloat162 bf162;

// ---------------- scratch (device globals) ----------------------------------
static __device__ float g_gb1[B*D2];
static __device__ float g_gb2[B*D2];
static __device__ float g_gx[B*D];
static __device__ float g_gm[B];
static __device__ float g_A1[B*D];
static __device__ float g_C1[B*D];
static __device__ float g_A2[B*D];
static __device__ float g_C2[B*D];
static __device__ float g_gx2sq[B*D];
static __device__ int   g_invp[NP];
static __device__ float g_imtok[(size_t)T*D];
static __device__ float g_qkv[(size_t)T*QS];
static __device__ float g_wi[(size_t)T*D];
static __device__ float g_wif[(size_t)T*D];
static __device__ float g_kv[B*NC*NH*HD*HD];
static __device__ float g_ks[B*NC*NH*HD];
static __device__ float g_bqkv[QS];
// bf16 activations
static __device__ bf16  g_xg16[(size_t)T*D];
static __device__ bf16  g_att16[(size_t)T*D];
static __device__ bf16  g_x216[(size_t)T*D];
static __device__ bf16  g_h116[(size_t)T*D4];
// bf16 weights
static __device__ bf16  g_wqkv16[QS*D];
static __device__ bf16  g_wo16[D*D];
static __device__ bf16  g_c1w16[D4*D];
static __device__ bf16  g_c2w16[D*D4];

// ---------------- helpers ----------------------------------------------------
__device__ __forceinline__ uint32_t sptr(const void* p) {
    return (uint32_t)__cvta_generic_to_shared(p);
}
__device__ __forceinline__ void cp16(uint32_t s, const void* g) {
    asm volatile("cp.async.cg.shared.global [%0], [%1], 16;\n" :: "r"(s), "l"(g));
}
__device__ __forceinline__ void cp_commit() {
    asm volatile("cp.async.commit_group;\n");
}
template<int N>
__device__ __forceinline__ void cp_wait() {
    asm volatile("cp.async.wait_group %0;\n" :: "n"(N));
}
__device__ __forceinline__ void mma16816(float* c, const uint32_t* a, const uint32_t* b) {
    asm volatile(
        "mma.sync.aligned.m16n8k16.row.col.f32.bf16.bf16.f32 "
        "{%0,%1,%2,%3}, {%4,%5,%6,%7}, {%8,%9}, {%0,%1,%2,%3};\n"
        : "+f"(c[0]), "+f"(c[1]), "+f"(c[2]), "+f"(c[3])
        : "r"(a[0]), "r"(a[1]), "r"(a[2]), "r"(a[3]), "r"(b[0]), "r"(b[1]));
}
__device__ __forceinline__ void ldsm4(uint32_t* r, uint32_t a) {
    asm volatile("ldmatrix.sync.aligned.m8n8.x4.shared.b16 {%0,%1,%2,%3}, [%4];"
        : "=r"(r[0]), "=r"(r[1]), "=r"(r[2]), "=r"(r[3]) : "r"(a));
}

__device__ __forceinline__ float blockReduce384(float v, float* sdata) {
    int tid = threadIdx.x;
    sdata[tid] = v;
    if (tid < 128) sdata[384 + tid] = 0.f;
    __syncthreads();
    #pragma unroll
    for (int s = 256; s >= 1; s >>= 1) {
        if (tid < s) sdata[tid] += sdata[tid + s];
        __syncthreads();
    }
    float r = sdata[0];
    __syncthreads();
    return r;
}

// ---------------- small kernels ----------------------------------------------
__global__ void k_invperm(const int* __restrict__ perm, int* __restrict__ invp) {
    int i = blockIdx.x * blockDim.x + threadIdx.x;
    if (i < NP) invp[perm[i]] = i;
}

__global__ void k_cvt(const float* __restrict__ src, bf16* __restrict__ dst, int n) {
    int i = blockIdx.x * blockDim.x + threadIdx.x;
    if (i < n) dst[i] = __float2bfloat16(src[i]);
}

__global__ void k_zero(float* __restrict__ p, int n) {
    int i = blockIdx.x * blockDim.x + threadIdx.x;
    if (i < n) p[i] = 0.f;
}

__global__ void k_catbias(const float* __restrict__ a, const float* __restrict__ b,
                          const float* __restrict__ c, float* __restrict__ o) {
    int i = blockIdx.x * blockDim.x + threadIdx.x;
    if (i < D) { o[i] = a[i]; o[D + i] = b[i]; o[2 * D + i] = c[i]; }
}

__global__ void k_film(const float* __restrict__ film,
                       const float* __restrict__ W1, const float* __restrict__ b1,
                       const float* __restrict__ W2, const float* __restrict__ b2,
                       float* __restrict__ gb1, float* __restrict__ gb2) {
    int o = blockIdx.x * blockDim.x + threadIdx.x;
    if (o >= 2 * B * D2) return;
    int which = o / (B * D2);
    int r = o % (B * D2);
    int b = r / D2, j = r % D2;
    const float* W = which ? W2 : W1;
    const float* bb = which ? b2 : b1;
    const float* f = film + b * FD;
    const float* w = W + (size_t)j * FD;
    float s = 0.f;
    #pragma unroll 8
    for (int i = 0; i < FD; i++) s += f[i] * w[i];
    s += bb[j];
    if (which) gb2[r] = s; else gb1[r] = s;
}

__global__ void k_gx_img(const float* __restrict__ img, float* __restrict__ gx) {
    __shared__ float sdata[256];
    int bd = blockIdx.x;
    const float* p = img + (size_t)bd * NP;
    float s = 0.f;
    for (int i = threadIdx.x; i < NP; i += 256) { float v = p[i]; s += v * v; }
    sdata[threadIdx.x] = s; __syncthreads();
    for (int st = 128; st >= 1; st >>= 1) {
        if (threadIdx.x < st) sdata[threadIdx.x] += sdata[threadIdx.x + st];
        __syncthreads();
    }
    if (threadIdx.x == 0) gx[bd] = sqrtf(sdata[0]);
}

__global__ void k_gmean(const float* __restrict__ gx, float* __restrict__ gm, int dosqrt) {
    __shared__ float sdata[512];
    int b = blockIdx.x;
    float v = gx[b * D + threadIdx.x];
    if (dosqrt) v = sqrtf(v);
    float s = blockReduce384(v, sdata);
    if (threadIdx.x == 0) gm[b] = s / (float)D;
}

__global__ void k_coef(const float* __restrict__ gx, const float* __restrict__ gm,
                       const float* __restrict__ gg, const float* __restrict__ gb_,
                       const float* __restrict__ gbmat,
                       float* __restrict__ A, float* __restrict__ C, int dosqrt) {
    int idx = blockIdx.x * blockDim.x + threadIdx.x;
    if (idx >= B * D) return;
    int b = idx / D, d = idx % D;
    float gv = gx[idx];
    if (dosqrt) gv = sqrtf(gv);
    float nx = gv / (gm[b] + 1e-6f);
    float gamma = gbmat[b * D2 + d];
    float beta  = gbmat[b * D2 + D + d];
    A[idx] = ((1.f + gg[d]) * nx + 1.f) * (1.f + gamma);
    C[idx] = gb_[d] * (1.f + gamma) + beta;
}

// transpose-gather: image [b,d,pix] -> token-major imtok fp32 + xg bf16 (adaln applied)
__global__ void __launch_bounds__(256) k_gather_t(
        const float* __restrict__ img, const int* __restrict__ invp,
        const float* __restrict__ A, const float* __restrict__ C,
        float* __restrict__ imtok, bf16* __restrict__ xg) {
    __shared__ float tile[64][65];
    __shared__ int sinv[64];
    int p0 = blockIdx.x * 64, d0 = blockIdx.y * 64, b = blockIdx.z;
    int tid = threadIdx.x;
    if (tid < 64) sinv[tid] = invp[p0 + tid];
    #pragma unroll
    for (int l = 0; l < 4; l++) {
        int j = tid + l * 256;
        int i = j >> 4, q = (j & 15) * 4;
        float4 v = *(const float4*)(img + ((size_t)(b * D + d0 + i)) * NP + p0 + q);
        tile[i][q + 0] = v.x; tile[i][q + 1] = v.y;
        tile[i][q + 2] = v.z; tile[i][q + 3] = v.w;
    }
    __syncthreads();
    #pragma unroll
    for (int l = 0; l < 4; l++) {
        int j = tid + l * 256;
        int jp = j >> 4, i4 = (j & 15) * 4;
        int t = sinv[jp];
        size_t o = ((size_t)(b * NP + t)) * D + d0 + i4;
        float vv[4], xv[4];
        #pragma unroll
        for (int r = 0; r < 4; r++) {
            vv[r] = tile[i4 + r][jp];
            int cidx = b * D + d0 + i4 + r;
            xv[r] = A[cidx] * vv[r] + C[cidx];
        }
        *(float4*)&imtok[o] = make_float4(vv[0], vv[1], vv[2], vv[3]);
        *(bf162*)&xg[o] = __floats2bfloat162_rn(xv[0], xv[1]);
        *(bf162*)&xg[o + 2] = __floats2bfloat162_rn(xv[2], xv[3]);
    }
}

// ---------------- bf16 tensor-core GEMM (ldmatrix + 3-stage cp.async) --------
// C[M,N] = act(A[M,K] @ W[N,K]^T + bias) [*scale + res], optional gx2 accum.
// A: [M,K] bf16 row-major, W: [N,K] bf16 row-major. BM=BN=128, BK=32, 256 thr.
#define LDT 40
#define STG 3
#define STAGE_E (128 * LDT)
#define GEMM_SMEM (STG * 2 * STAGE_E * 2)
template<typename OutT, bool SILU, bool RES, bool GX2>
__global__ void __launch_bounds__(256, 2) gemm_mma(
        const bf16* __restrict__ A, const bf16* __restrict__ W,
        const float* __restrict__ bias, const float* __restrict__ res,
        const float* __restrict__ scale, OutT* __restrict__ C,
        float* __restrict__ gx2sq, int M, int N, int K) {
    extern __shared__ bf16 smem[];
    bf16* sA = smem;                  // [STG][STAGE_E]
    bf16* sW = smem + STG * STAGE_E;  // [STG][STAGE_E]
    uint32_t sbA = sptr(sA), sbW = sptr(sW);
    int tid = threadIdx.x;
    int m0 = blockIdx.y * 128, n0 = blockIdx.x * 128;
    int lane = tid & 31, warp = tid >> 5;
    int g = lane >> 2, tg = lane & 3;
    int wm = warp >> 2, wn = warp & 3;
    int lane8 = lane & 7, laneg = lane >> 3;   // laneg 0..3

    // ldmatrix per-lane byte offsets within a stage
    uint32_t aOff[4], bOff[2];
    #pragma unroll
    for (int im = 0; im < 4; im++) {
        int row = wm * 64 + im * 16 + lane8 + (laneg & 1) * 8;
        int col = (laneg >> 1) * 8;
        aOff[im] = (uint32_t)(row * LDT + col) * 2;
    }
    #pragma unroll
    for (int p = 0; p < 2; p++) {
        int row = wn * 32 + p * 16 + lane8 + (laneg >> 1) * 8;
        int col = (laneg & 1) * 8;
        bOff[p] = (uint32_t)(row * LDT + col) * 2;
    }

    float acc[4][4][4];
    #pragma unroll
    for (int i = 0; i < 4; i++)
        #pragma unroll
        for (int j = 0; j < 4; j++)
            #pragma unroll
            for (int p = 0; p < 4; p++) acc[i][j][p] = 0.f;

    int nt = K / 32;
    auto issue = [&](int t) {
        if (t < nt) {
            int s = t % STG;
            int k0 = t * 32;
            #pragma unroll
            for (int l = 0; l < 2; l++) {
                int j = tid + l * 256;
                int row = j >> 2, q = (j & 3) * 8;
                cp16(sbA + (s * STAGE_E + row * LDT + q) * 2, A + (size_t)(m0 + row) * K + k0 + q);
                cp16(sbW + (s * STAGE_E + row * LDT + q) * 2, W + (size_t)(n0 + row) * K + k0 + q);
            }
        }
        cp_commit();
    };

    issue(0);
    issue(1);
    for (int t = 0; t < nt; t++) {
        cp_wait<STG - 2>();
        __syncthreads();
        int s = t % STG;
        uint32_t aBase = sbA + s * STAGE_E * 2;
        uint32_t wBase = sbW + s * STAGE_E * 2;
        #pragma unroll
        for (int kk = 0; kk < 32; kk += 16) {
            uint32_t af[4][4], bf[2][4];
            #pragma unroll
            for (int im = 0; im < 4; im++) ldsm4(af[im], aBase + aOff[im] + kk * 2);
            #pragma unroll
            for (int p = 0; p < 2; p++)    ldsm4(bf[p], wBase + bOff[p] + kk * 2);
            #pragma unroll
            for (int im = 0; im < 4; im++)
                #pragma unroll
                for (int in = 0; in < 4; in++)
                    mma16816(acc[im][in], af[im], &bf[in >> 1][(in & 1) * 2]);
        }
        __syncthreads();
        issue(t + 2);
    }

    // epilogue
    float sums[4][2];
    if (GX2) {
        #pragma unroll
        for (int in = 0; in < 4; in++) { sums[in][0] = 0.f; sums[in][1] = 0.f; }
    }
    #pragma unroll
    for (int im = 0; im < 4; im++) {
        int r0 = m0 + wm * 64 + im * 16 + g;
        #pragma unroll
        for (int in = 0; in < 4; in++) {
            int c = n0 + wn * 32 + in * 8 + tg * 2;
            float b0 = bias[c], b1 = bias[c + 1];
            float v00 = acc[im][in][0] + b0, v01 = acc[im][in][1] + b1;
            float v10 = acc[im][in][2] + b0, v11 = acc[im][in][3] + b1;
            if (SILU) {
                v00 = v00 / (1.f + expf(-v00)); v01 = v01 / (1.f + expf(-v01));
                v10 = v10 / (1.f + expf(-v10)); v11 = v11 / (1.f + expf(-v11));
            }
            if (RES) {
                float s0 = scale[c], s1 = scale[c + 1];
                float2 ra = *(const float2*)&res[(size_t)r0 * N + c];
                float2 rb = *(const float2*)&res[(size_t)(r0 + 8) * N + c];
                v00 = ra.x + v00 * s0; v01 = ra.y + v01 * s1;
                v10 = rb.x + v10 * s0; v11 = rb.y + v11 * s1;
            }
            if (GX2) {
                sums[in][0] += v00 * v00 + v10 * v10;
                sums[in][1] += v01 * v01 + v11 * v11;
            }
            if (sizeof(OutT) == 4) {
                *(float2*)((float*)C + (size_t)r0 * N + c) = make_float2(v00, v01);
                *(float2*)((float*)C + (size_t)(r0 + 8) * N + c) = make_float2(v10, v11);
            } else {
                *(bf162*)((bf16*)C + (size_t)r0 * N + c) = __floats2bfloat162_rn(v00, v01);
                *(bf162*)((bf16*)C + (size_t)(r0 + 8) * N + c) = __floats2bfloat162_rn(v10, v11);
            }
        }
    }
    if (GX2) {
        #pragma unroll
        for (int off = 4; off <= 16; off <<= 1) {
            #pragma unroll
            for (int in = 0; in < 4; in++) {
                sums[in][0] += __shfl_xor_sync(0xffffffff, sums[in][0], off);
                sums[in][1] += __shfl_xor_sync(0xffffffff, sums[in][1], off);
            }
        }
        if (lane < 4) {
            int b = m0 >> 12;
            #pragma unroll
            for (int in = 0; in < 4; in++) {
                int c = n0 + wn * 32 + in * 8 + tg * 2;
                atomicAdd(&gx2sq[b * D + c], sums[in][0]);
                atomicAdd(&gx2sq[b * D + c + 1], sums[in][1]);
            }
        }
    }
}

// per-token LayerNorm over D then elu+1 (in place), warp per token; y: 0=q, 1=k
__global__ void __launch_bounds__(256) k_lnelu(float* __restrict__ X,
        const float* __restrict__ gq, const float* __restrict__ bq_,
        const float* __restrict__ gk, const float* __restrict__ bk_) {
    int warp = threadIdx.x >> 5, lane = threadIdx.x & 31;
    int t = blockIdx.x * 8 + warp;
    int seg = blockIdx.y;
    const float* gam = seg ? gk : gq;
    const float* bet = seg ? bk_ : bq_;
    size_t base = (size_t)t * QS + seg * D;
    float v[12];
    float s = 0.f, s2 = 0.f;
    #pragma unroll
    for (int j = 0; j < 12; j++) {
        v[j] = X[base + j * 32 + lane];
        s += v[j]; s2 += v[j] * v[j];
    }
    #pragma unroll
    for (int o = 16; o >= 1; o >>= 1) {
        s  += __shfl_xor_sync(0xffffffff, s, o);
        s2 += __shfl_xor_sync(0xffffffff, s2, o);
    }
    float mean = s / (float)D;
    float var = s2 / (float)D - mean * mean;
    float rstd = rsqrtf(var + 1e-5f);
    #pragma unroll
    for (int j = 0; j < 12; j++) {
        int d = j * 32 + lane;
        float y = (v[j] - mean) * rstd * gam[d] + bet[d];
        X[base + d] = (y > 0.f) ? (y + 1.f) : expf(y);
    }
}

// kv[bh] = sum_i k_i outer v_i ; ksum[bh] = sum_i k_i   (qkv packed, stride QS)
__global__ void __launch_bounds__(256) k_attn_kv(const float* __restrict__ qkv,
                                                 float* __restrict__ kv,
                                                 float* __restrict__ ksum) {
    int bh = blockIdx.x;
    int h = bh & (NH - 1), bc = bh >> 3;
    __shared__ float sk[16][HD];
    __shared__ float sv[16][HD];
    int tid = threadIdx.x;
    float acc[9];
    #pragma unroll
    for (int p = 0; p < 9; p++) acc[p] = 0.f;
    float ks = 0.f;
    int base = tid * 9;
    int dp[9], ep[9];
    #pragma unroll
    for (int p = 0; p < 9; p++) { dp[p] = (base + p) / HD; ep[p] = (base + p) % HD; }

    for (int c = 0; c < GS / 16; c++) {
        int tt0 = bc * GS + c * 16;
        #pragma unroll
        for (int r = 0; r < 3; r++) {
            int j = r * 256 + tid;
            int ti = j / HD, d = j % HD;
            size_t row = (size_t)(tt0 + ti) * QS + h * HD + d;
            sk[ti][d] = qkv[row + D];
            sv[ti][d] = qkv[row + 2 * D];
        }
        __syncthreads();
        #pragma unroll 4
        for (int ti = 0; ti < 16; ti++) {
            #pragma unroll
            for (int p = 0; p < 9; p++) acc[p] += sk[ti][dp[p]] * sv[ti][ep[p]];
        }
        if (tid < HD) {
            #pragma unroll 4
            for (int ti = 0; ti < 16; ti++) ks += sk[ti][tid];
        }
        __syncthreads();
    }
    #pragma unroll
    for (int p = 0; p < 9; p++) kv[(size_t)bh * HD * HD + base + p] = acc[p];
    if (tid < HD) ksum[bh * HD + tid] = ks;
}

// out[t,h,e] = (q . kv[:,e]) / (q . ksum + 1e-8), bf16 output
__global__ void __launch_bounds__(256) k_attn_apply(const float* __restrict__ qkv,
                                                    const float* __restrict__ kv,
                                                    const float* __restrict__ ksum,
                                                    bf16* __restrict__ out) {
    int bh = blockIdx.x;
    int tile = blockIdx.y;
    int h = bh & (NH - 1), bc = bh >> 3;
    __shared__ float skv[HD * HD];
    __shared__ float sks[HD];
    __shared__ float sq[16][HD];
    int tid = threadIdx.x;
    for (int i = tid; i < HD * HD; i += 256) skv[i] = kv[(size_t)bh * HD * HD + i];
    if (tid < HD) sks[tid] = ksum[bh * HD + tid];
    __syncthreads();
    int t0 = bc * GS + tile * 64;
    for (int sub = 0; sub < 4; sub++) {
        int tt0 = t0 + sub * 16;
        #pragma unroll
        for (int r = 0; r < 3; r++) {
            int j = r * 256 + tid;
            int ti = j / HD, d = j % HD;
            sq[ti][d] = qkv[(size_t)(tt0 + ti) * QS + h * HD + d];
        }
        __syncthreads();
        #pragma unroll
        for (int r = 0; r < 3; r++) {
            int j = r * 256 + tid;
            int ti = j / HD, e = j % HD;
            float num = 0.f, den = 0.f;
            #pragma unroll
            for (int d = 0; d < HD; d++) {
                float qq = sq[ti][d];
                num += qq * skv[d * HD + e];
                den += qq * sks[d];
            }
            out[(size_t)(tt0 + ti) * D + h * HD + e] = __float2bfloat16(num / (den + 1e-8f));
        }
        __syncthreads();
    }
}

// x2 = A2[b,d]*wi + C2[b,d], bf16 output
__global__ void k_x2(const float* __restrict__ wi, const float* __restrict__ A,
                     const float* __restrict__ C, bf16* __restrict__ x2) {
    size_t idx = (size_t)blockIdx.x * 256 + threadIdx.x;
    int t = (int)(idx / D), d = (int)(idx % D);
    int b = t >> 12;
    x2[idx] = __float2bfloat16(A[b * D + d] * wi[idx] + C[b * D + d]);
}

// out[b,d,pix] = image[b,d,pix] + wif[token(pix), d] * final_scalar[d]
__global__ void __launch_bounds__(256) k_final_t(
        const float* __restrict__ img, const float* __restrict__ wif,
        const int* __restrict__ invp, const float* __restrict__ fs,
        float* __restrict__ out) {
    __shared__ float tile[64][65];
    __shared__ int sinv[64];
    int p0 = blockIdx.x * 64, d0 = blockIdx.y * 64, b = blockIdx.z;
    int tid = threadIdx.x;
    if (tid < 64) sinv[tid] = invp[p0 + tid];
    __syncthreads();
    #pragma unroll
    for (int l = 0; l < 4; l++) {
        int j = tid + l * 256;
        int jp = j >> 4, i4 = (j & 15) * 4;
        int t = sinv[jp];
        float4 v = *(const float4*)(wif + ((size_t)(b * NP + t)) * D + d0 + i4);
        tile[i4 + 0][jp] = v.x; tile[i4 + 1][jp] = v.y;
        tile[i4 + 2][jp] = v.z; tile[i4 + 3][jp] = v.w;
    }
    __syncthreads();
    #pragma unroll
    for (int l = 0; l < 4; l++) {
        int j = tid + l * 256;
        int i = j >> 4, q = (j & 15) * 4;
        size_t o = ((size_t)(b * D + d0 + i)) * NP + p0 + q;
        float4 im4 = *(const float4*)(img + o);
        float f = fs[d0 + i];
        float4 r;
        r.x = im4.x + tile[i][q + 0] * f;
        r.y = im4.y + tile[i][q + 1] * f;
        r.z = im4.z + tile[i][q + 2] * f;
        r.w = im4.w + tile[i][q + 3] * f;
        *(float4*)(out + o) = r;
    }
}

// ---------------- driver ----------------------------------------------------
extern "C" void kernel_launch(void* const* d_in, const int* in_sizes, int n_in,
                              void* d_out, int out_size) {
    const float* image  = (const float*)d_in[0];
    const float* film   = (const float*)d_in[1];
    const int*   perm   = (const int*)d_in[2];
    const float* Wq = (const float*)d_in[3];  const float* bq = (const float*)d_in[4];
    const float* Wk = (const float*)d_in[5];  const float* bk = (const float*)d_in[6];
    const float* Wv = (const float*)d_in[7];  const float* bv = (const float*)d_in[8];
    const float* Wo = (const float*)d_in[9];  const float* bo = (const float*)d_in[10];
    const float* lnq_g = (const float*)d_in[11]; const float* lnq_b = (const float*)d_in[12];
    const float* lnk_g = (const float*)d_in[13]; const float* lnk_b = (const float*)d_in[14];
    const float* ada1_W = (const float*)d_in[15]; const float* ada1_b = (const float*)d_in[16];
    const float* grn1_g = (const float*)d_in[17]; const float* grn1_b = (const float*)d_in[18];
    const float* ada2_W = (const float*)d_in[19]; const float* ada2_b = (const float*)d_in[20];
    const float* grn2_g = (const float*)d_in[21]; const float* grn2_b = (const float*)d_in[22];
    const float* conv1_W = (const float*)d_in[23]; const float* conv1_b = (const float*)d_in[24];
    const float* conv2_W = (const float*)d_in[25]; const float* conv2_b = (const float*)d_in[26];
    const float* cs  = (const float*)d_in[27];
    const float* ffs = (const float*)d_in[28];
    const float* fs  = (const float*)d_in[29];
    float* out = (float*)d_out;

    float *p_gb1, *p_gb2, *p_gx, *p_gm, *p_A1, *p_C1, *p_A2, *p_C2, *p_gx2sq;
    int* p_invp;
    float *p_imtok, *p_qkv, *p_wi, *p_wif, *p_kv, *p_ks, *p_bqkv;
    bf16 *p_xg16, *p_att16, *p_x216, *p_h116;
    bf16 *p_wqkv16, *p_wo16, *p_c1w16, *p_c2w16;
    cudaGetSymbolAddress((void**)&p_gb1, g_gb1);
    cudaGetSymbolAddress((void**)&p_gb2, g_gb2);
    cudaGetSymbolAddress((void**)&p_gx, g_gx);
    cudaGetSymbolAddress((void**)&p_gm, g_gm);
    cudaGetSymbolAddress((void**)&p_A1, g_A1);
    cudaGetSymbolAddress((void**)&p_C1, g_C1);
    cudaGetSymbolAddress((void**)&p_A2, g_A2);
    cudaGetSymbolAddress((void**)&p_C2, g_C2);
    cudaGetSymbolAddress((void**)&p_gx2sq, g_gx2sq);
    cudaGetSymbolAddress((void**)&p_invp, g_invp);
    cudaGetSymbolAddress((void**)&p_imtok, g_imtok);
    cudaGetSymbolAddress((void**)&p_qkv, g_qkv);
    cudaGetSymbolAddress((void**)&p_wi, g_wi);
    cudaGetSymbolAddress((void**)&p_wif, g_wif);
    cudaGetSymbolAddress((void**)&p_kv, g_kv);
    cudaGetSymbolAddress((void**)&p_ks, g_ks);
    cudaGetSymbolAddress((void**)&p_bqkv, g_bqkv);
    cudaGetSymbolAddress((void**)&p_xg16, g_xg16);
    cudaGetSymbolAddress((void**)&p_att16, g_att16);
    cudaGetSymbolAddress((void**)&p_x216, g_x216);
    cudaGetSymbolAddress((void**)&p_h116, g_h116);
    cudaGetSymbolAddress((void**)&p_wqkv16, g_wqkv16);
    cudaGetSymbolAddress((void**)&p_wo16, g_wo16);
    cudaGetSymbolAddress((void**)&p_c1w16, g_c1w16);
    cudaGetSymbolAddress((void**)&p_c2w16, g_c2w16);

    cudaFuncSetAttribute((const void*)gemm_mma<float,false,false,false>,
                         cudaFuncAttributeMaxDynamicSharedMemorySize, GEMM_SMEM);
    cudaFuncSetAttribute((const void*)gemm_mma<float,false,true,true>,
                         cudaFuncAttributeMaxDynamicSharedMemorySize, GEMM_SMEM);
    cudaFuncSetAttribute((const void*)gemm_mma<bf16,true,false,false>,
                         cudaFuncAttributeMaxDynamicSharedMemorySize, GEMM_SMEM);
    cudaFuncSetAttribute((const void*)gemm_mma<float,false,true,false>,
                         cudaFuncAttributeMaxDynamicSharedMemorySize, GEMM_SMEM);

    // weight conversions (cheap)
    k_cvt<<<(D*D + 255)/256, 256>>>(Wq, p_wqkv16, D*D);
    k_cvt<<<(D*D + 255)/256, 256>>>(Wk, p_wqkv16 + D*D, D*D);
    k_cvt<<<(D*D + 255)/256, 256>>>(Wv, p_wqkv16 + 2*D*D, D*D);
    k_cvt<<<(D*D + 255)/256, 256>>>(Wo, p_wo16, D*D);
    k_cvt<<<(D4*D + 255)/256, 256>>>(conv1_W, p_c1w16, D4*D);
    k_cvt<<<(D*D4 + 255)/256, 256>>>(conv2_W, p_c2w16, D*D4);
    k_catbias<<<2, 256>>>(bq, bk, bv, p_bqkv);
    k_zero<<<12, 256>>>(p_gx2sq, B*D);

    k_invperm<<<16, 256>>>(perm, p_invp);
    k_film<<<48, 256>>>(film, ada1_W, ada1_b, ada2_W, ada2_b, p_gb1, p_gb2);
    k_gx_img<<<B * D, 256>>>(image, p_gx);
    k_gmean<<<B, 384>>>(p_gx, p_gm, 0);
    k_coef<<<(B * D + 255) / 256, 256>>>(p_gx, p_gm, grn1_g, grn1_b, p_gb1, p_A1, p_C1, 0);
    k_gather_t<<<dim3(NP/64, D/64, B), 256>>>(image, p_invp, p_A1, p_C1, p_imtok, p_xg16);

    // packed QKV GEMM: [T, 1152]
    gemm_mma<float,false,false,false><<<dim3(QS/128, T/128), 256, GEMM_SMEM>>>(
        p_xg16, p_wqkv16, p_bqkv, nullptr, nullptr, p_qkv, nullptr, T, QS, D);

    k_lnelu<<<dim3(T/8, 2), 256>>>(p_qkv, lnq_g, lnq_b, lnk_g, lnk_b);

    k_attn_kv<<<B * NC * NH, 256>>>(p_qkv, p_kv, p_ks);
    k_attn_apply<<<dim3(B * NC * NH, 16), 256>>>(p_qkv, p_kv, p_ks, p_att16);

    // wi = imtok + (attn@Wo^T + bo) * cs ; also gx2sq += wi^2 (per b,d)
    gemm_mma<float,false,true,true><<<dim3(3, T/128), 256, GEMM_SMEM>>>(
        p_att16, p_wo16, bo, p_imtok, cs, p_wi, p_gx2sq, T, D, D);

    k_gmean<<<B, 384>>>(p_gx2sq, p_gm, 1);
    k_coef<<<(B * D + 255) / 256, 256>>>(p_gx2sq, p_gm, grn2_g, grn2_b, p_gb2, p_A2, p_C2, 1);
    k_x2<<<(int)(((size_t)T*D) / 256), 256>>>(p_wi, p_A2, p_C2, p_x216);

    // h1 = silu(x2 @ conv1^T + b1)
    gemm_mma<bf16,true,false,false><<<dim3(12, T/128), 256, GEMM_SMEM>>>(
        p_x216, p_c1w16, conv1_b, nullptr, nullptr, p_h116, nullptr, T, D4, D);
    // wif = wi + (h1 @ conv2^T + b2) * ffs
    gemm_mma<float,false,true,false><<<dim3(3, T/128), 256, GEMM_SMEM>>>(
        p_h116, p_c2w16, conv2_b, p_wi, ffs, p_wif, nullptr, T, D, D4);

    k_final_t<<<dim3(NP/64, D/64, B), 256>>>(image, p_wif, p_invp, fs, out);
}

// round 6
// speedup vs baseline: 3.9032x; 1.0339x over previous
#include <cuda_runtime.h>
#include <cuda_bf16.h>
#include <math.h>
#include <stdint.h>

#define B   8
#define D   384
#define FD  256
#define NP  4096
#define NH  8
#define NC  4
#define HD  48
#define GS  1024
#define T   (B*NP)     /* 32768 tokens */
#define D4  1536
#define D2  768
#define QS  1152       /* packed qkv row stride */

typedef __nv_bfloat16 bf16;
typedef __nv_bfloat162 bf162;

// ---------------- scratch (device globals) ----------------------------------
static __device__ float g_gb1[B*D2];
static __device__ float g_gb2[B*D2];
static __device__ float g_gx[B*D];
static __device__ float g_A1[B*D];
static __device__ float g_C1[B*D];
static __device__ float g_A2[B*D];
static __device__ float g_C2[B*D];
static __device__ float g_gx2sq[B*D];
static __device__ int   g_invp[NP];
static __device__ float g_imtok[(size_t)T*D];
static __device__ float g_wi[(size_t)T*D];
static __device__ float g_wif[(size_t)T*D];
static __device__ float g_kv[B*NC*NH*HD*HD];
static __device__ float g_ks[B*NC*NH*HD];
static __device__ float g_bqkv[QS];
// bf16 activations
static __device__ bf16  g_qkv16[(size_t)T*QS];
static __device__ bf16  g_xg16[(size_t)T*D];
static __device__ bf16  g_att16[(size_t)T*D];
static __device__ bf16  g_x216[(size_t)T*D];
static __device__ bf16  g_h116[(size_t)T*D4];
// bf16 weights
static __device__ bf16  g_wqkv16[QS*D];
static __device__ bf16  g_wo16[D*D];
static __device__ bf16  g_c1w16[D4*D];
static __device__ bf16  g_c2w16[D*D4];

// ---------------- helpers ----------------------------------------------------
__device__ __forceinline__ uint32_t sptr(const void* p) {
    return (uint32_t)__cvta_generic_to_shared(p);
}
__device__ __forceinline__ void cp16(uint32_t s, const void* g) {
    asm volatile("cp.async.cg.shared.global [%0], [%1], 16;\n" :: "r"(s), "l"(g));
}
__device__ __forceinline__ void cp_commit() {
    asm volatile("cp.async.commit_group;\n");
}
template<int N>
__device__ __forceinline__ void cp_wait() {
    asm volatile("cp.async.wait_group %0;\n" :: "n"(N));
}
__device__ __forceinline__ void mma16816(float* c, const uint32_t* a, const uint32_t* b) {
    asm volatile(
        "mma.sync.aligned.m16n8k16.row.col.f32.bf16.bf16.f32 "
        "{%0,%1,%2,%3}, {%4,%5,%6,%7}, {%8,%9}, {%0,%1,%2,%3};\n"
        : "+f"(c[0]), "+f"(c[1]), "+f"(c[2]), "+f"(c[3])
        : "r"(a[0]), "r"(a[1]), "r"(a[2]), "r"(a[3]), "r"(b[0]), "r"(b[1]));
}
__device__ __forceinline__ void ldsm4(uint32_t* r, uint32_t a) {
    asm volatile("ldmatrix.sync.aligned.m8n8.x4.shared.b16 {%0,%1,%2,%3}, [%4];"
        : "=r"(r[0]), "=r"(r[1]), "=r"(r[2]), "=r"(r[3]) : "r"(a));
}

__device__ __forceinline__ float blockReduce384(float v, float* sdata) {
    int tid = threadIdx.x;
    sdata[tid] = v;
    if (tid < 128) sdata[384 + tid] = 0.f;
    __syncthreads();
    #pragma unroll
    for (int s = 256; s >= 1; s >>= 1) {
        if (tid < s) sdata[tid] += sdata[tid + s];
        __syncthreads();
    }
    float r = sdata[0];
    __syncthreads();
    return r;
}

// ---------------- fused prep: all weight cvt + bias cat + zero + invperm -----
#define NWQKV (3*D*D)          /* 442368 */
#define NWO   (D*D)            /* 147456 */
#define NC1   (D4*D)           /* 589824 */
#define NC2   (D*D4)           /* 589824 */
#define PREP_TOT (NWQKV + NWO + NC1 + NC2 + QS + B*D + NP)
__global__ void k_prep(const float* __restrict__ Wq, const float* __restrict__ Wk,
                       const float* __restrict__ Wv, const float* __restrict__ Wo,
                       const float* __restrict__ c1, const float* __restrict__ c2,
                       const float* __restrict__ bq, const float* __restrict__ bk,
                       const float* __restrict__ bv,
                       const int* __restrict__ perm,
                       bf16* __restrict__ wqkv, bf16* __restrict__ wo,
                       bf16* __restrict__ c1o, bf16* __restrict__ c2o,
                       float* __restrict__ bqkv, float* __restrict__ gx2sq,
                       int* __restrict__ invp) {
    int i = blockIdx.x * blockDim.x + threadIdx.x;
    if (i < NWQKV) {
        int seg = i / (D*D), r = i % (D*D);
        const float* W = (seg == 0) ? Wq : (seg == 1) ? Wk : Wv;
        wqkv[i] = __float2bfloat16(W[r]);
        return;
    }
    i -= NWQKV;
    if (i < NWO) { wo[i] = __float2bfloat16(Wo[i]); return; }
    i -= NWO;
    if (i < NC1) { c1o[i] = __float2bfloat16(c1[i]); return; }
    i -= NC1;
    if (i < NC2) { c2o[i] = __float2bfloat16(c2[i]); return; }
    i -= NC2;
    if (i < QS) {
        bqkv[i] = (i < D) ? bq[i] : (i < 2*D) ? bk[i - D] : bv[i - 2*D];
        return;
    }
    i -= QS;
    if (i < B*D) { gx2sq[i] = 0.f; return; }
    i -= B*D;
    if (i < NP) invp[perm[i]] = i;
}

__global__ void k_film(const float* __restrict__ film,
                       const float* __restrict__ W1, const float* __restrict__ b1,
                       const float* __restrict__ W2, const float* __restrict__ b2,
                       float* __restrict__ gb1, float* __restrict__ gb2) {
    int o = blockIdx.x * blockDim.x + threadIdx.x;
    if (o >= 2 * B * D2) return;
    int which = o / (B * D2);
    int r = o % (B * D2);
    int b = r / D2, j = r % D2;
    const float* W = which ? W2 : W1;
    const float* bb = which ? b2 : b1;
    const float* f = film + b * FD;
    const float* w = W + (size_t)j * FD;
    float s = 0.f;
    #pragma unroll 8
    for (int i = 0; i < FD; i++) s += f[i] * w[i];
    s += bb[j];
    if (which) gb2[r] = s; else gb1[r] = s;
}

__global__ void k_gx_img(const float* __restrict__ img, float* __restrict__ gx) {
    __shared__ float sdata[256];
    int bd = blockIdx.x;
    const float* p = img + (size_t)bd * NP;
    float s = 0.f;
    for (int i = threadIdx.x; i < NP; i += 256) { float v = p[i]; s += v * v; }
    sdata[threadIdx.x] = s; __syncthreads();
    for (int st = 128; st >= 1; st >>= 1) {
        if (threadIdx.x < st) sdata[threadIdx.x] += sdata[threadIdx.x + st];
        __syncthreads();
    }
    if (threadIdx.x == 0) gx[bd] = sqrtf(sdata[0]);
}

// fused: per-batch mean of gx (opt sqrt) then adaln coefficients. 8 blocks x 384.
__global__ void k_gmean_coef(const float* __restrict__ gx,
                             const float* __restrict__ gg, const float* __restrict__ gb_,
                             const float* __restrict__ gbmat,
                             float* __restrict__ A, float* __restrict__ C, int dosqrt) {
    __shared__ float sdata[512];
    int b = blockIdx.x, d = threadIdx.x;
    float gv = gx[b * D + d];
    if (dosqrt) gv = sqrtf(gv);
    float s = blockReduce384(gv, sdata);
    float gm = s / (float)D;
    float nx = gv / (gm + 1e-6f);
    float gamma = gbmat[b * D2 + d];
    float beta  = gbmat[b * D2 + D + d];
    A[b * D + d] = ((1.f + gg[d]) * nx + 1.f) * (1.f + gamma);
    C[b * D + d] = gb_[d] * (1.f + gamma) + beta;
}

// transpose-gather: image [b,d,pix] -> token-major imtok fp32 + xg bf16
__global__ void __launch_bounds__(256) k_gather_t(
        const float* __restrict__ img, const int* __restrict__ invp,
        const float* __restrict__ A, const float* __restrict__ C,
        float* __restrict__ imtok, bf16* __restrict__ xg) {
    __shared__ float tile[64][65];
    __shared__ int sinv[64];
    int p0 = blockIdx.x * 64, d0 = blockIdx.y * 64, b = blockIdx.z;
    int tid = threadIdx.x;
    if (tid < 64) sinv[tid] = invp[p0 + tid];
    #pragma unroll
    for (int l = 0; l < 4; l++) {
        int j = tid + l * 256;
        int i = j >> 4, q = (j & 15) * 4;
        float4 v = *(const float4*)(img + ((size_t)(b * D + d0 + i)) * NP + p0 + q);
        tile[i][q + 0] = v.x; tile[i][q + 1] = v.y;
        tile[i][q + 2] = v.z; tile[i][q + 3] = v.w;
    }
    __syncthreads();
    #pragma unroll
    for (int l = 0; l < 4; l++) {
        int j = tid + l * 256;
        int jp = j >> 4, i4 = (j & 15) * 4;
        int t = sinv[jp];
        size_t o = ((size_t)(b * NP + t)) * D + d0 + i4;
        float vv[4], xv[4];
        #pragma unroll
        for (int r = 0; r < 4; r++) {
            vv[r] = tile[i4 + r][jp];
            int cidx = b * D + d0 + i4 + r;
            xv[r] = A[cidx] * vv[r] + C[cidx];
        }
        *(float4*)&imtok[o] = make_float4(vv[0], vv[1], vv[2], vv[3]);
        *(bf162*)&xg[o] = __floats2bfloat162_rn(xv[0], xv[1]);
        *(bf162*)&xg[o + 2] = __floats2bfloat162_rn(xv[2], xv[3]);
    }
}

// ---------------- bf16 tensor-core GEMM (ldmatrix + 3-stage cp.async) --------
#define LDT 40
#define STG 3
#define STAGE_E (128 * LDT)
#define GEMM_SMEM (STG * 2 * STAGE_E * 2)
template<typename OutT, bool SILU, bool RES, bool GX2>
__global__ void __launch_bounds__(256, 2) gemm_mma(
        const bf16* __restrict__ A, const bf16* __restrict__ W,
        const float* __restrict__ bias, const float* __restrict__ res,
        const float* __restrict__ scale, OutT* __restrict__ C,
        float* __restrict__ gx2sq, int M, int N, int K) {
    extern __shared__ bf16 smem[];
    bf16* sA = smem;
    bf16* sW = smem + STG * STAGE_E;
    uint32_t sbA = sptr(sA), sbW = sptr(sW);
    int tid = threadIdx.x;
    int m0 = blockIdx.y * 128, n0 = blockIdx.x * 128;
    int lane = tid & 31, warp = tid >> 5;
    int g = lane >> 2, tg = lane & 3;
    int wm = warp >> 2, wn = warp & 3;
    int lane8 = lane & 7, laneg = lane >> 3;

    uint32_t aOff[4], bOff[2];
    #pragma unroll
    for (int im = 0; im < 4; im++) {
        int row = wm * 64 + im * 16 + lane8 + (laneg & 1) * 8;
        int col = (laneg >> 1) * 8;
        aOff[im] = (uint32_t)(row * LDT + col) * 2;
    }
    #pragma unroll
    for (int p = 0; p < 2; p++) {
        int row = wn * 32 + p * 16 + lane8 + (laneg >> 1) * 8;
        int col = (laneg & 1) * 8;
        bOff[p] = (uint32_t)(row * LDT + col) * 2;
    }

    float acc[4][4][4];
    #pragma unroll
    for (int i = 0; i < 4; i++)
        #pragma unroll
        for (int j = 0; j < 4; j++)
            #pragma unroll
            for (int p = 0; p < 4; p++) acc[i][j][p] = 0.f;

    int nt = K / 32;
    auto issue = [&](int t) {
        if (t < nt) {
            int s = t % STG;
            int k0 = t * 32;
            #pragma unroll
            for (int l = 0; l < 2; l++) {
                int j = tid + l * 256;
                int row = j >> 2, q = (j & 3) * 8;
                cp16(sbA + (s * STAGE_E + row * LDT + q) * 2, A + (size_t)(m0 + row) * K + k0 + q);
                cp16(sbW + (s * STAGE_E + row * LDT + q) * 2, W + (size_t)(n0 + row) * K + k0 + q);
            }
        }
        cp_commit();
    };

    issue(0);
    issue(1);
    for (int t = 0; t < nt; t++) {
        cp_wait<STG - 2>();
        __syncthreads();
        int s = t % STG;
        uint32_t aBase = sbA + s * STAGE_E * 2;
        uint32_t wBase = sbW + s * STAGE_E * 2;
        #pragma unroll
        for (int kk = 0; kk < 32; kk += 16) {
            uint32_t af[4][4], bf[2][4];
            #pragma unroll
            for (int im = 0; im < 4; im++) ldsm4(af[im], aBase + aOff[im] + kk * 2);
            #pragma unroll
            for (int p = 0; p < 2; p++)    ldsm4(bf[p], wBase + bOff[p] + kk * 2);
            #pragma unroll
            for (int im = 0; im < 4; im++)
                #pragma unroll
                for (int in = 0; in < 4; in++)
                    mma16816(acc[im][in], af[im], &bf[in >> 1][(in & 1) * 2]);
        }
        __syncthreads();
        issue(t + 2);
    }

    // epilogue
    float sums[4][2];
    if (GX2) {
        #pragma unroll
        for (int in = 0; in < 4; in++) { sums[in][0] = 0.f; sums[in][1] = 0.f; }
    }
    #pragma unroll
    for (int im = 0; im < 4; im++) {
        int r0 = m0 + wm * 64 + im * 16 + g;
        #pragma unroll
        for (int in = 0; in < 4; in++) {
            int c = n0 + wn * 32 + in * 8 + tg * 2;
            float b0 = bias[c], b1 = bias[c + 1];
            float v00 = acc[im][in][0] + b0, v01 = acc[im][in][1] + b1;
            float v10 = acc[im][in][2] + b0, v11 = acc[im][in][3] + b1;
            if (SILU) {
                v00 = v00 / (1.f + expf(-v00)); v01 = v01 / (1.f + expf(-v01));
                v10 = v10 / (1.f + expf(-v10)); v11 = v11 / (1.f + expf(-v11));
            }
            if (RES) {
                float s0 = scale[c], s1 = scale[c + 1];
                float2 ra = *(const float2*)&res[(size_t)r0 * N + c];
                float2 rb = *(const float2*)&res[(size_t)(r0 + 8) * N + c];
                v00 = ra.x + v00 * s0; v01 = ra.y + v01 * s1;
                v10 = rb.x + v10 * s0; v11 = rb.y + v11 * s1;
            }
            if (GX2) {
                sums[in][0] += v00 * v00 + v10 * v10;
                sums[in][1] += v01 * v01 + v11 * v11;
            }
            if (sizeof(OutT) == 4) {
                *(float2*)((float*)C + (size_t)r0 * N + c) = make_float2(v00, v01);
                *(float2*)((float*)C + (size_t)(r0 + 8) * N + c) = make_float2(v10, v11);
            } else {
                *(bf162*)((bf16*)C + (size_t)r0 * N + c) = __floats2bfloat162_rn(v00, v01);
                *(bf162*)((bf16*)C + (size_t)(r0 + 8) * N + c) = __floats2bfloat162_rn(v10, v11);
            }
        }
    }
    if (GX2) {
        #pragma unroll
        for (int off = 4; off <= 16; off <<= 1) {
            #pragma unroll
            for (int in = 0; in < 4; in++) {
                sums[in][0] += __shfl_xor_sync(0xffffffff, sums[in][0], off);
                sums[in][1] += __shfl_xor_sync(0xffffffff, sums[in][1], off);
            }
        }
        if (lane < 4) {
            int b = m0 >> 12;
            #pragma unroll
            for (int in = 0; in < 4; in++) {
                int c = n0 + wn * 32 + in * 8 + tg * 2;
                atomicAdd(&gx2sq[b * D + c], sums[in][0]);
                atomicAdd(&gx2sq[b * D + c + 1], sums[in][1]);
            }
        }
    }
}

// per-token LayerNorm over D then elu+1, bf16 in/out, warp per token; y: 0=q, 1=k
__global__ void __launch_bounds__(256) k_lnelu(bf16* __restrict__ X,
        const float* __restrict__ gq, const float* __restrict__ bq_,
        const float* __restrict__ gk, const float* __restrict__ bk_) {
    int warp = threadIdx.x >> 5, lane = threadIdx.x & 31;
    int t = blockIdx.x * 8 + warp;
    int seg = blockIdx.y;
    const float* gam = seg ? gk : gq;
    const float* bet = seg ? bk_ : bq_;
    size_t base = (size_t)t * QS + seg * D;
    float v[12];
    float s = 0.f, s2 = 0.f;
    #pragma unroll
    for (int j = 0; j < 12; j++) {
        v[j] = __bfloat162float(X[base + j * 32 + lane]);
        s += v[j]; s2 += v[j] * v[j];
    }
    #pragma unroll
    for (int o = 16; o >= 1; o >>= 1) {
        s  += __shfl_xor_sync(0xffffffff, s, o);
        s2 += __shfl_xor_sync(0xffffffff, s2, o);
    }
    float mean = s / (float)D;
    float var = s2 / (float)D - mean * mean;
    float rstd = rsqrtf(var + 1e-5f);
    #pragma unroll
    for (int j = 0; j < 12; j++) {
        int d = j * 32 + lane;
        float y = (v[j] - mean) * rstd * gam[d] + bet[d];
        X[base + d] = __float2bfloat16((y > 0.f) ? (y + 1.f) : expf(y));
    }
}

// kv[bh] = sum_i k_i outer v_i ; ksum[bh] = sum_i k_i   (bf16 qkv, stride QS)
__global__ void __launch_bounds__(256) k_attn_kv(const bf16* __restrict__ qkv,
                                                 float* __restrict__ kv,
                                                 float* __restrict__ ksum) {
    int bh = blockIdx.x;
    int h = bh & (NH - 1), bc = bh >> 3;
    __shared__ float sk[16][HD];
    __shared__ float sv[16][HD];
    int tid = threadIdx.x;
    float acc[9];
    #pragma unroll
    for (int p = 0; p < 9; p++) acc[p] = 0.f;
    float ks = 0.f;
    int base = tid * 9;
    int dp[9], ep[9];
    #pragma unroll
    for (int p = 0; p < 9; p++) { dp[p] = (base + p) / HD; ep[p] = (base + p) % HD; }

    for (int c = 0; c < GS / 16; c++) {
        int tt0 = bc * GS + c * 16;
        #pragma unroll
        for (int r = 0; r < 3; r++) {
            int j = r * 256 + tid;
            int ti = j / HD, d = j % HD;
            size_t row = (size_t)(tt0 + ti) * QS + h * HD + d;
            sk[ti][d] = __bfloat162float(qkv[row + D]);
            sv[ti][d] = __bfloat162float(qkv[row + 2 * D]);
        }
        __syncthreads();
        #pragma unroll 4
        for (int ti = 0; ti < 16; ti++) {
            #pragma unroll
            for (int p = 0; p < 9; p++) acc[p] += sk[ti][dp[p]] * sv[ti][ep[p]];
        }
        if (tid < HD) {
            #pragma unroll 4
            for (int ti = 0; ti < 16; ti++) ks += sk[ti][tid];
        }
        __syncthreads();
    }
    #pragma unroll
    for (int p = 0; p < 9; p++) kv[(size_t)bh * HD * HD + base + p] = acc[p];
    if (tid < HD) ksum[bh * HD + tid] = ks;
}

// out[t,h,e] = (q . kv[:,e]) / (q . ksum + 1e-8), bf16 output
__global__ void __launch_bounds__(256) k_attn_apply(const bf16* __restrict__ qkv,
                                                    const float* __restrict__ kv,
                                                    const float* __restrict__ ksum,
                                                    bf16* __restrict__ out) {
    int bh = blockIdx.x;
    int tile = blockIdx.y;
    int h = bh & (NH - 1), bc = bh >> 3;
    __shared__ float skv[HD * HD];
    __shared__ float sks[HD];
    __shared__ float sq[16][HD];
    int tid = threadIdx.x;
    for (int i = tid; i < HD * HD; i += 256) skv[i] = kv[(size_t)bh * HD * HD + i];
    if (tid < HD) sks[tid] = ksum[bh * HD + tid];
    __syncthreads();
    int t0 = bc * GS + tile * 64;
    for (int sub = 0; sub < 4; sub++) {
        int tt0 = t0 + sub * 16;
        #pragma unroll
        for (int r = 0; r < 3; r++) {
            int j = r * 256 + tid;
            int ti = j / HD, d = j % HD;
            sq[ti][d] = __bfloat162float(qkv[(size_t)(tt0 + ti) * QS + h * HD + d]);
        }
        __syncthreads();
        #pragma unroll
        for (int r = 0; r < 3; r++) {
            int j = r * 256 + tid;
            int ti = j / HD, e = j % HD;
            float num = 0.f, den = 0.f;
            #pragma unroll
            for (int d = 0; d < HD; d++) {
                float qq = sq[ti][d];
                num += qq * skv[d * HD + e];
                den += qq * sks[d];
            }
            out[(size_t)(tt0 + ti) * D + h * HD + e] = __float2bfloat16(num / (den + 1e-8f));
        }
        __syncthreads();
    }
}

// x2 = A2[b,d]*wi + C2[b,d], bf16 output
__global__ void k_x2(const float* __restrict__ wi, const float* __restrict__ A,
                     const float* __restrict__ C, bf16* __restrict__ x2) {
    size_t idx = (size_t)blockIdx.x * 256 + threadIdx.x;
    int t = (int)(idx / D), d = (int)(idx % D);
    int b = t >> 12;
    x2[idx] = __float2bfloat16(A[b * D + d] * wi[idx] + C[b * D + d]);
}

// out[b,d,pix] = image[b,d,pix] + wif[token(pix), d] * final_scalar[d]
__global__ void __launch_bounds__(256) k_final_t(
        const float* __restrict__ img, const float* __restrict__ wif,
        const int* __restrict__ invp, const float* __restrict__ fs,
        float* __restrict__ out) {
    __shared__ float tile[64][65];
    __shared__ int sinv[64];
    int p0 = blockIdx.x * 64, d0 = blockIdx.y * 64, b = blockIdx.z;
    int tid = threadIdx.x;
    if (tid < 64) sinv[tid] = invp[p0 + tid];
    __syncthreads();
    #pragma unroll
    for (int l = 0; l < 4; l++) {
        int j = tid + l * 256;
        int jp = j >> 4, i4 = (j & 15) * 4;
        int t = sinv[jp];
        float4 v = *(const float4*)(wif + ((size_t)(b * NP + t)) * D + d0 + i4);
        tile[i4 + 0][jp] = v.x; tile[i4 + 1][jp] = v.y;
        tile[i4 + 2][jp] = v.z; tile[i4 + 3][jp] = v.w;
    }
    __syncthreads();
    #pragma unroll
    for (int l = 0; l < 4; l++) {
        int j = tid + l * 256;
        int i = j >> 4, q = (j & 15) * 4;
        size_t o = ((size_t)(b * D + d0 + i)) * NP + p0 + q;
        float4 im4 = *(const float4*)(img + o);
        float f = fs[d0 + i];
        float4 r;
        r.x = im4.x + tile[i][q + 0] * f;
        r.y = im4.y + tile[i][q + 1] * f;
        r.z = im4.z + tile[i][q + 2] * f;
        r.w = im4.w + tile[i][q + 3] * f;
        *(float4*)(out + o) = r;
    }
}

// ---------------- driver ----------------------------------------------------
extern "C" void kernel_launch(void* const* d_in, const int* in_sizes, int n_in,
                              void* d_out, int out_size) {
    const float* image  = (const float*)d_in[0];
    const float* film   = (const float*)d_in[1];
    const int*   perm   = (const int*)d_in[2];
    const float* Wq = (const float*)d_in[3];  const float* bq = (const float*)d_in[4];
    const float* Wk = (const float*)d_in[5];  const float* bk = (const float*)d_in[6];
    const float* Wv = (const float*)d_in[7];  const float* bv = (const float*)d_in[8];
    const float* Wo = (const float*)d_in[9];  const float* bo = (const float*)d_in[10];
    const float* lnq_g = (const float*)d_in[11]; const float* lnq_b = (const float*)d_in[12];
    const float* lnk_g = (const float*)d_in[13]; const float* lnk_b = (const float*)d_in[14];
    const float* ada1_W = (const float*)d_in[15]; const float* ada1_b = (const float*)d_in[16];
    const float* grn1_g = (const float*)d_in[17]; const float* grn1_b = (const float*)d_in[18];
    const float* ada2_W = (const float*)d_in[19]; const float* ada2_b = (const float*)d_in[20];
    const float* grn2_g = (const float*)d_in[21]; const float* grn2_b = (const float*)d_in[22];
    const float* conv1_W = (const float*)d_in[23]; const float* conv1_b = (const float*)d_in[24];
    const float* conv2_W = (const float*)d_in[25]; const float* conv2_b = (const float*)d_in[26];
    const float* cs  = (const float*)d_in[27];
    const float* ffs = (const float*)d_in[28];
    const float* fs  = (const float*)d_in[29];
    float* out = (float*)d_out;

    float *p_gb1, *p_gb2, *p_gx, *p_A1, *p_C1, *p_A2, *p_C2, *p_gx2sq;
    int* p_invp;
    float *p_imtok, *p_wi, *p_wif, *p_kv, *p_ks, *p_bqkv;
    bf16 *p_qkv16, *p_xg16, *p_att16, *p_x216, *p_h116;
    bf16 *p_wqkv16, *p_wo16, *p_c1w16, *p_c2w16;
    cudaGetSymbolAddress((void**)&p_gb1, g_gb1);
    cudaGetSymbolAddress((void**)&p_gb2, g_gb2);
    cudaGetSymbolAddress((void**)&p_gx, g_gx);
    cudaGetSymbolAddress((void**)&p_A1, g_A1);
    cudaGetSymbolAddress((void**)&p_C1, g_C1);
    cudaGetSymbolAddress((void**)&p_A2, g_A2);
    cudaGetSymbolAddress((void**)&p_C2, g_C2);
    cudaGetSymbolAddress((void**)&p_gx2sq, g_gx2sq);
    cudaGetSymbolAddress((void**)&p_invp, g_invp);
    cudaGetSymbolAddress((void**)&p_imtok, g_imtok);
    cudaGetSymbolAddress((void**)&p_wi, g_wi);
    cudaGetSymbolAddress((void**)&p_wif, g_wif);
    cudaGetSymbolAddress((void**)&p_kv, g_kv);
    cudaGetSymbolAddress((void**)&p_ks, g_ks);
    cudaGetSymbolAddress((void**)&p_bqkv, g_bqkv);
    cudaGetSymbolAddress((void**)&p_qkv16, g_qkv16);
    cudaGetSymbolAddress((void**)&p_xg16, g_xg16);
    cudaGetSymbolAddress((void**)&p_att16, g_att16);
    cudaGetSymbolAddress((void**)&p_x216, g_x216);
    cudaGetSymbolAddress((void**)&p_h116, g_h116);
    cudaGetSymbolAddress((void**)&p_wqkv16, g_wqkv16);
    cudaGetSymbolAddress((void**)&p_wo16, g_wo16);
    cudaGetSymbolAddress((void**)&p_c1w16, g_c1w16);
    cudaGetSymbolAddress((void**)&p_c2w16, g_c2w16);

    cudaFuncSetAttribute((const void*)gemm_mma<bf16,false,false,false>,
                         cudaFuncAttributeMaxDynamicSharedMemorySize, GEMM_SMEM);
    cudaFuncSetAttribute((const void*)gemm_mma<float,false,true,true>,
                         cudaFuncAttributeMaxDynamicSharedMemorySize, GEMM_SMEM);
    cudaFuncSetAttribute((const void*)gemm_mma<bf16,true,false,false>,
                         cudaFuncAttributeMaxDynamicSharedMemorySize, GEMM_SMEM);
    cudaFuncSetAttribute((const void*)gemm_mma<float,false,true,false>,
                         cudaFuncAttributeMaxDynamicSharedMemorySize, GEMM_SMEM);

    // launch 0: all prep fused
    k_prep<<<(PREP_TOT + 255) / 256, 256>>>(Wq, Wk, Wv, Wo, conv1_W, conv2_W,
        bq, bk, bv, perm, p_wqkv16, p_wo16, p_c1w16, p_c2w16,
        p_bqkv, p_gx2sq, p_invp);
    // launch 1
    k_film<<<48, 256>>>(film, ada1_W, ada1_b, ada2_W, ada2_b, p_gb1, p_gb2);
    // launch 2
    k_gx_img<<<B * D, 256>>>(image, p_gx);
    // launch 3
    k_gmean_coef<<<B, 384>>>(p_gx, grn1_g, grn1_b, p_gb1, p_A1, p_C1, 0);
    // launch 4
    k_gather_t<<<dim3(NP/64, D/64, B), 256>>>(image, p_invp, p_A1, p_C1, p_imtok, p_xg16);
    // launch 5: packed QKV GEMM (profiled by ncu -s 5 -c 1)
    gemm_mma<bf16,false,false,false><<<dim3(QS/128, T/128), 256, GEMM_SMEM>>>(
        p_xg16, p_wqkv16, p_bqkv, nullptr, nullptr, p_qkv16, nullptr, T, QS, D);

    k_lnelu<<<dim3(T/8, 2), 256>>>(p_qkv16, lnq_g, lnq_b, lnk_g, lnk_b);

    k_attn_kv<<<B * NC * NH, 256>>>(p_qkv16, p_kv, p_ks);
    k_attn_apply<<<dim3(B * NC * NH, 16), 256>>>(p_qkv16, p_kv, p_ks, p_att16);

    // wi = imtok + (attn@Wo^T + bo) * cs ; also gx2sq += wi^2 (per b,d)
    gemm_mma<float,false,true,true><<<dim3(3, T/128), 256, GEMM_SMEM>>>(
        p_att16, p_wo16, bo, p_imtok, cs, p_wi, p_gx2sq, T, D, D);

    k_gmean_coef<<<B, 384>>>(p_gx2sq, grn2_g, grn2_b, p_gb2, p_A2, p_C2, 1);
    k_x2<<<(int)(((size_t)T*D) / 256), 256>>>(p_wi, p_A2, p_C2, p_x216);

    // h1 = silu(x2 @ conv1^T + b1)
    gemm_mma<bf16,true,false,false><<<dim3(12, T/128), 256, GEMM_SMEM>>>(
        p_x216, p_c1w16, conv1_b, nullptr, nullptr, p_h116, nullptr, T, D4, D);
    // wif = wi + (h1 @ conv2^T + b2) * ffs
    gemm_mma<float,false,true,false><<<dim3(3, T/128), 256, GEMM_SMEM>>>(
        p_h116, p_c2w16, conv2_b, p_wi, ffs, p_wif, nullptr, T, D, D4);

    k_final_t<<<dim3(NP/64, D/64, B), 256>>>(image, p_wif, p_invp, fs, out);
}